// round 9
// baseline (speedup 1.0000x reference)
#include <cuda_runtime.h>
#include <cuda_bf16.h>
#include <cstdint>

// ---------------------------------------------------------------------------
// Shapes (fixed by the dataset)
// ---------------------------------------------------------------------------
#define MB   4096
#define DIN  512
#define HID  2048

// ---------------------------------------------------------------------------
// Device scratch (int8 slices + scales + fp32 intermediates)
// ---------------------------------------------------------------------------
__device__ int8_t g_xd0[(size_t)MB * DIN],  g_xd1[(size_t)MB * DIN];
__device__ int8_t g_w1d0[(size_t)HID * DIN], g_w1d1[(size_t)HID * DIN];
__device__ int8_t g_w2d0[(size_t)HID * HID], g_w2d1[(size_t)HID * HID];
__device__ int8_t g_h1d0[(size_t)MB * HID],  g_h1d1[(size_t)MB * HID];
__device__ float g_wt[(size_t)HID * HID];      // fp32 transpose staging
__device__ float g_h1[(size_t)MB * HID];
__device__ float g_h2[(size_t)MB * HID];
__device__ float g_sx[MB], g_sw1[HID], g_sw2[HID], g_sh1[MB];
__device__ float g_scores[MB];

// ---------------------------------------------------------------------------
// Helpers
// ---------------------------------------------------------------------------
__device__ __forceinline__ uint32_t smem_u32(const void* p) {
    uint32_t a;
    asm("{ .reg .u64 t; cvta.to.shared.u64 t, %1; cvt.u32.u64 %0, t; }"
        : "=r"(a) : "l"(p));
    return a;
}

#define SW128(o) ((o) ^ (((o) >> 3) & 0x70))

#define CPA16(smem, gptr) \
    asm volatile("cp.async.cg.shared.global [%0], [%1], 16;" \
                 :: "r"(smem), "l"(gptr))

#define LDMX4(r0, r1, r2, r3, addr) \
    asm volatile("ldmatrix.sync.aligned.m8n8.x4.shared.b16 {%0,%1,%2,%3}, [%4];" \
                 : "=r"(r0), "=r"(r1), "=r"(r2), "=r"(r3) : "r"(addr))

// s8 x s8 -> s32, m16n8k32
#define MMAS8(c, a0, a1, a2, a3, b0, b1) \
    asm volatile("mma.sync.aligned.m16n8k32.row.col.s32.s8.s8.s32 " \
                 "{%0,%1,%2,%3}, {%4,%5,%6,%7}, {%8,%9}, {%0,%1,%2,%3};" \
                 : "+r"((c)[0]), "+r"((c)[1]), "+r"((c)[2]), "+r"((c)[3]) \
                 : "r"(a0), "r"(a1), "r"(a2), "r"(a3), "r"(b0), "r"(b1))

// ---------------------------------------------------------------------------
// fp32 transpose: W [K,N] -> T [N,K]
// ---------------------------------------------------------------------------
__global__ void transpose_f32(const float* __restrict__ W,
                              float* __restrict__ T, int K, int N)
{
    __shared__ float t[32][33];
    int n0 = blockIdx.x * 32, k0 = blockIdx.y * 32;
    int tx = threadIdx.x, ty = threadIdx.y;
    #pragma unroll
    for (int r = ty; r < 32; r += 8)
        t[r][tx] = W[(size_t)(k0 + r) * N + n0 + tx];
    __syncthreads();
    #pragma unroll
    for (int r = ty; r < 32; r += 8)
        T[(size_t)(n0 + r) * K + k0 + tx] = t[tx][r];
}

// ---------------------------------------------------------------------------
// Row quantization: a ~= s*(d0 + d1/256), s = rowmax/127. One block per row.
// ---------------------------------------------------------------------------
__global__ __launch_bounds__(256)
void quant_rows(const float* __restrict__ in,
                char4* __restrict__ d0, char4* __restrict__ d1,
                float* __restrict__ scale, int K)
{
    const int row = blockIdx.x;
    const int tid = threadIdx.x;
    const float4* src = (const float4*)(in + (size_t)row * K);
    const int K4 = K >> 2;

    float mx = 0.0f;
    for (int i = tid; i < K4; i += 256) {
        float4 v = src[i];
        mx = fmaxf(mx, fmaxf(fmaxf(fabsf(v.x), fabsf(v.y)),
                             fmaxf(fabsf(v.z), fabsf(v.w))));
    }
    #pragma unroll
    for (int o = 16; o > 0; o >>= 1)
        mx = fmaxf(mx, __shfl_xor_sync(0xffffffffu, mx, o));
    __shared__ float red[8];
    if ((tid & 31) == 0) red[tid >> 5] = mx;
    __syncthreads();
    if (tid < 32) {
        float m = (tid < 8) ? red[tid] : 0.0f;
        #pragma unroll
        for (int o = 4; o > 0; o >>= 1)
            m = fmaxf(m, __shfl_xor_sync(0xffffffffu, m, o));
        if (tid == 0) red[0] = m;
    }
    __syncthreads();
    mx = red[0];

    const float s    = (mx > 1e-30f) ? mx / 127.0f : 1.0f;
    const float sinv = (mx > 1e-30f) ? 127.0f / mx : 0.0f;
    if (tid == 0) scale[row] = s;

    for (int i = tid; i < K4; i += 256) {
        float4 v = src[i];
        float q[4] = {v.x * sinv, v.y * sinv, v.z * sinv, v.w * sinv};
        char c0[4], c1[4];
        #pragma unroll
        for (int e = 0; e < 4; e++) {
            int i0 = __float2int_rn(q[e]);
            float r = q[e] - (float)i0;
            int i1 = __float2int_rn(r * 256.0f);
            i1 = max(-127, min(127, i1));
            c0[e] = (char)i0;
            c1[e] = (char)i1;
        }
        d0[(size_t)row * K4 + i] = make_char4(c0[0], c0[1], c0[2], c0[3]);
        d1[(size_t)row * K4 + i] = make_char4(c1[0], c1[1], c1[2], c1[3]);
    }
}

// ---------------------------------------------------------------------------
// int8 GEMM: out = relu(sA[m]*sB[n]*(acc0 + acc1/256) + bias[n])
// A slices [M,K] K-major int8; B slices [N,K] K-major int8.
// CTA 128x128, 512 threads, warp grid 4x4, warp tile 32x32, KC=128 bytes,
// 2-stage cp.async pipeline, m16n8k32 s8 IMMA.
// ---------------------------------------------------------------------------
#define BM 128
#define BN 128
#define KC 128
#define S_A0 0
#define S_A1 16384
#define S_B0 32768
#define S_B1 49152
#define STAGE_BYTES 65536
#define GEMM_SMEM (2 * STAGE_BYTES)   // 131072
#define NTHREADS 512
#define ISCALE (1.0f / 256.0f)

__global__ __launch_bounds__(NTHREADS, 1)
void gemm_i8(const int8_t* __restrict__ Ad0, const int8_t* __restrict__ Ad1,
             const int8_t* __restrict__ Bd0, const int8_t* __restrict__ Bd1,
             const float* __restrict__ sA, const float* __restrict__ sB,
             const float* __restrict__ bias,
             int K, int Npitch, float* __restrict__ outF)
{
    extern __shared__ char smem[];
    const uint32_t sb = smem_u32(smem);

    const int tid   = threadIdx.x;
    const int lane  = tid & 31;
    const int w     = tid >> 5;        // 0..15
    const int warpM = w >> 2;          // 0..3 (32 rows)
    const int warpN = w & 3;           // 0..3 (32 cols)
    const int g     = lane >> 2;
    const int tig   = lane & 3;

    const int rowA0 = blockIdx.y * BM;
    const int colB0 = blockIdx.x * BN;
    const int nch   = K / KC;

    int acc0[2][4][4], acc1[2][4][4];
    #pragma unroll
    for (int mf = 0; mf < 2; mf++)
        #pragma unroll
        for (int nf = 0; nf < 4; nf++)
            #pragma unroll
            for (int e = 0; e < 4; e++) {
                acc0[mf][nf][e] = 0;
                acc1[mf][nf][e] = 0;
            }

    auto load_chunk = [&](int j, int st) {
        const uint32_t stage = sb + st * STAGE_BYTES;
        const size_t cOff = (size_t)j * KC;   // byte offset (int8)
        #pragma unroll
        for (int u = 0; u < 8; u++) {
            const int seg  = u * NTHREADS + tid;   // 0..4095
            const int tile = seg >> 10;            // 0:A0 1:A1 2:B0 3:B1
            const int r    = (seg & 1023) >> 3;    // 0..127
            const int s    = (seg & 7) << 4;       // 0..112
            const uint32_t sw = SW128(r * 128 + s);
            const int8_t* base;
            size_t go;
            if (tile == 0)      { base = Ad0; go = (size_t)(rowA0 + r) * K; }
            else if (tile == 1) { base = Ad1; go = (size_t)(rowA0 + r) * K; }
            else if (tile == 2) { base = Bd0; go = (size_t)(colB0 + r) * K; }
            else                { base = Bd1; go = (size_t)(colB0 + r) * K; }
            CPA16(stage + tile * 16384 + sw, (const char*)(base + go + cOff) + s);
        }
        asm volatile("cp.async.commit_group;");
    };

    // ldmatrix lane addressing: row = base + (lane&7) + ((lane>>3)&1)*8,
    // kb = ((lane>>4)&1)*16  (same pattern for s8 A and B fragments)
    const int lrow = (lane & 7) + ((lane >> 3) & 1) * 8;
    const int lkb  = ((lane >> 4) & 1) * 16;

    load_chunk(0, 0);

    for (int j = 0; j < nch; j++) {
        __syncthreads();
        if (j + 1 < nch) {
            load_chunk(j + 1, (j + 1) & 1);
            asm volatile("cp.async.wait_group 1;" ::: "memory");
        } else {
            asm volatile("cp.async.wait_group 0;" ::: "memory");
        }
        __syncthreads();

        const uint32_t stage = sb + (j & 1) * STAGE_BYTES;

        #pragma unroll
        for (int ks = 0; ks < 4; ks++) {
            const int kbyte = ks * 32 + lkb;

            uint32_t a0f[2][4], a1f[2][4];
            #pragma unroll
            for (int mf = 0; mf < 2; mf++) {
                const uint32_t off = SW128((warpM * 32 + mf * 16 + lrow) * 128 + kbyte);
                LDMX4(a0f[mf][0], a0f[mf][1], a0f[mf][2], a0f[mf][3],
                      stage + S_A0 + off);
                LDMX4(a1f[mf][0], a1f[mf][1], a1f[mf][2], a1f[mf][3],
                      stage + S_A1 + off);
            }
            #pragma unroll
            for (int nb = 0; nb < 2; nb++) {
                const uint32_t off = SW128((warpN * 32 + nb * 16 + lrow) * 128 + kbyte);
                uint32_t bh[4], blr[4];
                LDMX4(bh[0], bh[1], bh[2], bh[3], stage + S_B0 + off);
                LDMX4(blr[0], blr[1], blr[2], blr[3], stage + S_B1 + off);
                // nfrag = nb*2 + half; b regs: (r_half, r_{2+half})
                #pragma unroll
                for (int half = 0; half < 2; half++) {
                    const int nf = nb * 2 + half;
                    #pragma unroll
                    for (int mf = 0; mf < 2; mf++) {
                        MMAS8(acc0[mf][nf], a0f[mf][0], a0f[mf][1], a0f[mf][2], a0f[mf][3],
                              bh[half], bh[2 + half]);
                        MMAS8(acc1[mf][nf], a0f[mf][0], a0f[mf][1], a0f[mf][2], a0f[mf][3],
                              blr[half], blr[2 + half]);
                        MMAS8(acc1[mf][nf], a1f[mf][0], a1f[mf][1], a1f[mf][2], a1f[mf][3],
                              bh[half], bh[2 + half]);
                    }
                }
            }
        }
    }

    // ---- epilogue: rescale + bias + relu, fp32 out ----
    #pragma unroll
    for (int mf = 0; mf < 2; mf++) {
        const int r0 = rowA0 + warpM * 32 + mf * 16 + g;
        const int r1 = r0 + 8;
        const float sa0 = __ldg(sA + r0);
        const float sa1 = __ldg(sA + r1);
        #pragma unroll
        for (int nf = 0; nf < 4; nf++) {
            const int col = colB0 + warpN * 32 + nf * 8 + tig * 2;
            const float sb0 = __ldg(sB + col);
            const float sb1 = __ldg(sB + col + 1);
            const float bx = __ldg(bias + col);
            const float by = __ldg(bias + col + 1);
            float v00 = sa0 * sb0 * ((float)acc0[mf][nf][0] + (float)acc1[mf][nf][0] * ISCALE) + bx;
            float v01 = sa0 * sb1 * ((float)acc0[mf][nf][1] + (float)acc1[mf][nf][1] * ISCALE) + by;
            float v10 = sa1 * sb0 * ((float)acc0[mf][nf][2] + (float)acc1[mf][nf][2] * ISCALE) + bx;
            float v11 = sa1 * sb1 * ((float)acc0[mf][nf][3] + (float)acc1[mf][nf][3] * ISCALE) + by;
            v00 = fmaxf(v00, 0.0f); v01 = fmaxf(v01, 0.0f);
            v10 = fmaxf(v10, 0.0f); v11 = fmaxf(v11, 0.0f);
            *(float2*)(outF + (size_t)r0 * Npitch + col) = make_float2(v00, v01);
            *(float2*)(outF + (size_t)r1 * Npitch + col) = make_float2(v10, v11);
        }
    }
}

// ---------------------------------------------------------------------------
// GEMV: scores[r] = dot(H[r,:], w) + b
// ---------------------------------------------------------------------------
__global__ __launch_bounds__(256)
void gemv_scores(const float* __restrict__ H,
                 const float* __restrict__ w,
                 const float* __restrict__ b3,
                 float* __restrict__ scores,
                 int rows, int K)
{
    const int gwarp = (blockIdx.x * blockDim.x + threadIdx.x) >> 5;
    const int lane  = threadIdx.x & 31;
    if (gwarp >= rows) return;

    const float4* r4 = (const float4*)(H + (size_t)gwarp * K);
    const float4* w4 = (const float4*)w;
    const int K4 = K >> 2;

    float acc = 0.0f;
    for (int t = lane; t < K4; t += 32) {
        float4 a = r4[t];
        float4 b = w4[t];
        acc += a.x * b.x + a.y * b.y + a.z * b.z + a.w * b.w;
    }
    #pragma unroll
    for (int o = 16; o > 0; o >>= 1)
        acc += __shfl_down_sync(0xffffffffu, acc, o);
    if (lane == 0) scores[gwarp] = acc + b3[0];
}

// ---------------------------------------------------------------------------
// soft_rank (parallel PAV)
// ---------------------------------------------------------------------------
__device__ __forceinline__ int pav_merge(int Lbase, int nl, int Rbase, int nr,
                                         int* __restrict__ pst,
                                         int* __restrict__ pcn,
                                         float* __restrict__ psm)
{
    int len = nl;
    for (int t = 0; t < nr; t++) {
        int   cs = pst[Rbase + t];
        int   cc = pcn[Rbase + t];
        float cm = psm[Rbase + t];
        while (len > 0) {
            float ts = psm[Lbase + len - 1];
            int   tc = pcn[Lbase + len - 1];
            if (ts * (float)cc < cm * (float)tc) {
                cm += ts; cc += tc; cs = pst[Lbase + len - 1];
                len--;
            } else break;
        }
        pst[Lbase + len] = cs;
        pcn[Lbase + len] = cc;
        psm[Lbase + len] = cm;
        len++;
    }
    return len;
}

__global__ void softrank_kernel(const float* __restrict__ scores,
                                float* __restrict__ out,
                                int n)
{
    extern __shared__ float smf[];
    float* s   = smf;
    float* psm = s + n;
    int*   idx = (int*)(psm + n);
    int*   pst = idx + n;
    int*   pcn = pst + n;
    int*   cA  = pcn + n;
    int*   cB  = cA + n / 2;

    const int tid = threadIdx.x;
    const int nt  = blockDim.x;

    for (int i = tid; i < n; i += nt) { s[i] = scores[i]; idx[i] = i; }
    __syncthreads();

    for (int k = 2; k <= n; k <<= 1) {
        for (int j = k >> 1; j > 0; j >>= 1) {
            for (int i = tid; i < n; i += nt) {
                int ixj = i ^ j;
                if (ixj > i) {
                    bool up = ((i & k) == 0);
                    float a = s[i], b = s[ixj];
                    bool sw = up ? (a < b) : (a > b);
                    if (sw) {
                        s[i] = b; s[ixj] = a;
                        int t = idx[i]; idx[i] = idx[ixj]; idx[ixj] = t;
                    }
                }
            }
            __syncthreads();
        }
    }

    for (int i = tid; i < n; i += nt) {
        pst[i] = i;
        pcn[i] = 1;
        psm[i] = s[i] - (float)(n - i);
    }
    __syncthreads();

    for (int g2 = tid; g2 < n / 2; g2 += nt)
        cA[g2] = pav_merge(2 * g2, 1, 2 * g2 + 1, 1, pst, pcn, psm);
    __syncthreads();

    int* cCur = cA;
    int* cNxt = cB;
    for (int L = 2; (1 << L) <= n; L++) {
        const int half = 1 << (L - 1);
        const int nm = n >> L;
        for (int g2 = tid; g2 < nm; g2 += nt)
            cNxt[g2] = pav_merge((g2 << L), cCur[2 * g2],
                                 (g2 << L) + half, cCur[2 * g2 + 1],
                                 pst, pcn, psm);
        __syncthreads();
        int* t = cCur; cCur = cNxt; cNxt = t;
    }
    const int P = cCur[0];

    for (int i = tid; i < n; i += nt) {
        int lo = 0, hi = P - 1;
        while (lo < hi) {
            int mid = (lo + hi + 1) >> 1;
            if (pst[mid] <= i) lo = mid; else hi = mid - 1;
        }
        float dual = psm[lo] / (float)pcn[lo];
        out[idx[i]] = s[i] - dual;
        out[n + i]  = scores[i];
    }
}

// ---------------------------------------------------------------------------
// Launch
// ---------------------------------------------------------------------------
extern "C" void kernel_launch(void* const* d_in, const int* in_sizes, int n_in,
                              void* d_out, int out_size)
{
    const float* x  = (const float*)d_in[0];
    const float* W1 = (const float*)d_in[1];
    const float* b1 = (const float*)d_in[2];
    const float* W2 = (const float*)d_in[3];
    const float* b2 = (const float*)d_in[4];
    const float* W3 = (const float*)d_in[5];
    const float* b3 = (const float*)d_in[6];
    float* out = (float*)d_out;

    int8_t *xd0, *xd1, *w1d0, *w1d1, *w2d0, *w2d1, *h1d0, *h1d1;
    float *wt, *h1, *h2, *sx, *sw1, *sw2, *sh1, *sc;
    cudaGetSymbolAddress((void**)&xd0,  g_xd0);
    cudaGetSymbolAddress((void**)&xd1,  g_xd1);
    cudaGetSymbolAddress((void**)&w1d0, g_w1d0);
    cudaGetSymbolAddress((void**)&w1d1, g_w1d1);
    cudaGetSymbolAddress((void**)&w2d0, g_w2d0);
    cudaGetSymbolAddress((void**)&w2d1, g_w2d1);
    cudaGetSymbolAddress((void**)&h1d0, g_h1d0);
    cudaGetSymbolAddress((void**)&h1d1, g_h1d1);
    cudaGetSymbolAddress((void**)&wt,   g_wt);
    cudaGetSymbolAddress((void**)&h1,   g_h1);
    cudaGetSymbolAddress((void**)&h2,   g_h2);
    cudaGetSymbolAddress((void**)&sx,   g_sx);
    cudaGetSymbolAddress((void**)&sw1,  g_sw1);
    cudaGetSymbolAddress((void**)&sw2,  g_sw2);
    cudaGetSymbolAddress((void**)&sh1,  g_sh1);
    cudaGetSymbolAddress((void**)&sc,   g_scores);

    cudaFuncSetAttribute(gemm_i8,
                         cudaFuncAttributeMaxDynamicSharedMemorySize, GEMM_SMEM);

    // quantize x
    quant_rows<<<MB, 256>>>(x, (char4*)xd0, (char4*)xd1, sx, DIN);
    // W1 [DIN,HID] -> Wt [HID,DIN] -> quantize
    transpose_f32<<<dim3(HID / 32, DIN / 32), dim3(32, 8)>>>(W1, wt, DIN, HID);
    quant_rows<<<HID, 256>>>(wt, (char4*)w1d0, (char4*)w1d1, sw1, DIN);
    // W2 [HID,HID] -> Wt -> quantize
    transpose_f32<<<dim3(HID / 32, HID / 32), dim3(32, 8)>>>(W2, wt, HID, HID);
    quant_rows<<<HID, 256>>>(wt, (char4*)w2d0, (char4*)w2d1, sw2, HID);

    // layer 1: h1 = relu(x @ W1 + b1)
    gemm_i8<<<dim3(HID / BN, MB / BM), NTHREADS, GEMM_SMEM>>>(
        xd0, xd1, w1d0, w1d1, sx, sw1, b1, DIN, HID, h1);
    // quantize h1
    quant_rows<<<MB, 256>>>(h1, (char4*)h1d0, (char4*)h1d1, sh1, HID);
    // layer 2: h2 = relu(h1 @ W2 + b2)
    gemm_i8<<<dim3(HID / BN, MB / BM), NTHREADS, GEMM_SMEM>>>(
        h1d0, h1d1, w2d0, w2d1, sh1, sw2, b2, HID, HID, h2);

    // layer 3: GEMV
    gemv_scores<<<(MB + 7) / 8, 256>>>(h2, W3, b3, sc, MB, HID);

    // soft_rank
    {
        size_t smem = (size_t)MB * 6 * sizeof(float);
        cudaFuncSetAttribute(softrank_kernel,
                             cudaFuncAttributeMaxDynamicSharedMemorySize,
                             (int)smem);
        softrank_kernel<<<1, 1024, smem>>>(sc, out, MB);
    }
}

// round 10
// speedup vs baseline: 2.9209x; 2.9209x over previous
#include <cuda_runtime.h>
#include <cuda_bf16.h>
#include <cstdint>

// ---------------------------------------------------------------------------
// Shapes (fixed by the dataset)
// ---------------------------------------------------------------------------
#define MB   4096
#define DIN  512
#define HID  2048

// ---------------------------------------------------------------------------
// Device scratch
// ---------------------------------------------------------------------------
__device__ __nv_bfloat16 g_xhi[(size_t)MB * DIN],  g_xlo[(size_t)MB * DIN];
__device__ __nv_bfloat16 g_w1hi[(size_t)HID * DIN], g_w1lo[(size_t)HID * DIN];
__device__ __nv_bfloat16 g_w2hi[(size_t)HID * HID], g_w2lo[(size_t)HID * HID];
__device__ __nv_bfloat16 g_h1hi[(size_t)MB * HID],  g_h1lo[(size_t)MB * HID];
__device__ float g_scores[MB];

// ---------------------------------------------------------------------------
// Helpers
// ---------------------------------------------------------------------------
__device__ __forceinline__ uint32_t smem_u32(const void* p) {
    uint32_t a;
    asm("{ .reg .u64 t; cvta.to.shared.u64 t, %1; cvt.u32.u64 %0, t; }"
        : "=r"(a) : "l"(p));
    return a;
}

#define SW128(o) ((o) ^ (((o) >> 3) & 0x70))

#define CPA16(smem, gptr) \
    asm volatile("cp.async.cg.shared.global [%0], [%1], 16;" \
                 :: "r"(smem), "l"(gptr))

#define LDMX4(r0, r1, r2, r3, addr) \
    asm volatile("ldmatrix.sync.aligned.m8n8.x4.shared.b16 {%0,%1,%2,%3}, [%4];" \
                 : "=r"(r0), "=r"(r1), "=r"(r2), "=r"(r3) : "r"(addr))

#define MMA16816(c, a0, a1, a2, a3, b0, b1) \
    asm volatile("mma.sync.aligned.m16n8k16.row.col.f32.bf16.bf16.f32 " \
                 "{%0,%1,%2,%3}, {%4,%5,%6,%7}, {%8,%9}, {%0,%1,%2,%3};" \
                 : "+f"((c)[0]), "+f"((c)[1]), "+f"((c)[2]), "+f"((c)[3]) \
                 : "r"(a0), "r"(a1), "r"(a2), "r"(a3), "r"(b0), "r"(b1))

// ---------------------------------------------------------------------------
// Conversion kernels: fp32 -> (bf16 hi, bf16 lo)
// ---------------------------------------------------------------------------
__global__ void split_rows(const float* __restrict__ in,
                           __nv_bfloat16* __restrict__ hi,
                           __nv_bfloat16* __restrict__ lo, int n)
{
    int i = (blockIdx.x * blockDim.x + threadIdx.x) * 4;
    if (i >= n) return;
    float4 v = *(const float4*)(in + i);
    float vv[4] = {v.x, v.y, v.z, v.w};
    #pragma unroll
    for (int k = 0; k < 4; k++) {
        __nv_bfloat16 h = __float2bfloat16(vv[k]);
        hi[i + k] = h;
        lo[i + k] = __float2bfloat16(vv[k] - __bfloat162float(h));
    }
}

// W [K,N] row-major -> T hi/lo [N,K], 64-wide k tiles for coalesced writes.
// grid (N/32, K/64), block (32,8)
__global__ void transpose_split64(const float* __restrict__ W,
                                  __nv_bfloat16* __restrict__ Thi,
                                  __nv_bfloat16* __restrict__ Tlo,
                                  int K, int N)
{
    __shared__ float t[64][33];
    const int n0 = blockIdx.x * 32, k0 = blockIdx.y * 64;
    const int tx = threadIdx.x, ty = threadIdx.y;
    #pragma unroll
    for (int r = ty; r < 64; r += 8)
        t[r][tx] = W[(size_t)(k0 + r) * N + n0 + tx];
    __syncthreads();
    #pragma unroll
    for (int nr = ty; nr < 32; nr += 8) {
        float v0 = t[tx * 2][nr];
        float v1 = t[tx * 2 + 1][nr];
        __nv_bfloat162 h, l;
        h.x = __float2bfloat16(v0);
        h.y = __float2bfloat16(v1);
        l.x = __float2bfloat16(v0 - __bfloat162float(h.x));
        l.y = __float2bfloat16(v1 - __bfloat162float(h.y));
        const size_t o = (size_t)(n0 + nr) * K + k0 + tx * 2;
        *(__nv_bfloat162*)(Thi + o) = h;
        *(__nv_bfloat162*)(Tlo + o) = l;
    }
}

__global__ void zero_scores(float* __restrict__ s)
{
    s[blockIdx.x * 1024 + threadIdx.x] = 0.0f;
}

// ---------------------------------------------------------------------------
// mma.sync GEMM (R6 structure): D = relu(A @ B^T + bias), split-bf16.
// CTA 128x256, 256 threads, warp grid 2x4, warp tile 64x64, KC=64, 2-stage.
// mode=1: write split bf16 h1.  mode=0: fused GEMV — dot relu'd tile with
// W3 and atomicAdd per-row partials into scores (no h2 materialization).
// ---------------------------------------------------------------------------
#define BM 128
#define BN 256
#define KC 64
#define S_A_HI 0
#define S_A_LO 16384
#define S_B_HI 32768
#define S_B_LO 65536
#define STAGE_BYTES 98304
#define GEMM_SMEM (2 * STAGE_BYTES)   // 196608

__global__ __launch_bounds__(256, 1)
void gemm_mma(const __nv_bfloat16* __restrict__ Ahi,
              const __nv_bfloat16* __restrict__ Alo,
              const __nv_bfloat16* __restrict__ Bhi,
              const __nv_bfloat16* __restrict__ Blo,
              const float* __restrict__ bias,
              int K, int Npitch, int mode,
              __nv_bfloat16* __restrict__ outHi,
              __nv_bfloat16* __restrict__ outLo,
              const float* __restrict__ w3,
              float* __restrict__ scores)
{
    extern __shared__ char smem[];
    const uint32_t sb = smem_u32(smem);

    const int tid   = threadIdx.x;
    const int lane  = tid & 31;
    const int w     = tid >> 5;
    const int warpM = w >> 2;          // 0..1  (64 rows each)
    const int warpN = w & 3;           // 0..3  (64 cols each)
    const int g     = lane >> 2;
    const int tig   = lane & 3;

    const int rowA0 = blockIdx.y * BM;
    const int colB0 = blockIdx.x * BN;
    const int nch   = K / KC;

    float acc[4][8][4];
    #pragma unroll
    for (int mf = 0; mf < 4; mf++)
        #pragma unroll
        for (int nf = 0; nf < 8; nf++)
            #pragma unroll
            for (int e = 0; e < 4; e++)
                acc[mf][nf][e] = 0.0f;

    auto load_chunk = [&](int j, int st) {
        const uint32_t stage = sb + st * STAGE_BYTES;
        const size_t cOff = (size_t)j * KC;
        #pragma unroll
        for (int u = 0; u < 8; u++) {
            const int seg = u * 256 + tid;
            const int r = seg >> 4;
            const int halfsel = (seg >> 3) & 1;
            const int s = (seg & 7) << 4;
            const uint32_t sw = SW128(r * 128 + s);
            const __nv_bfloat16* base = halfsel ? Alo : Ahi;
            const char* gp = (const char*)(base + (size_t)(rowA0 + r) * K + cOff) + s;
            CPA16(stage + (halfsel ? S_A_LO : S_A_HI) + sw, gp);
        }
        #pragma unroll
        for (int u = 0; u < 16; u++) {
            const int seg = u * 256 + tid;
            const int r = seg >> 4;
            const int halfsel = (seg >> 3) & 1;
            const int s = (seg & 7) << 4;
            const uint32_t sw = SW128(r * 128 + s);
            const __nv_bfloat16* base = halfsel ? Blo : Bhi;
            const char* gp = (const char*)(base + (size_t)(colB0 + r) * K + cOff) + s;
            CPA16(stage + (halfsel ? S_B_LO : S_B_HI) + sw, gp);
        }
        asm volatile("cp.async.commit_group;");
    };

    const int aRow = warpM * 64 + (lane & 7) + ((lane >> 3) & 1) * 8;
    const int aKb  = ((lane >> 4) & 1) * 16;
    const int bRowBase = warpN * 64 + ((lane >> 4) & 1) * 8 + (lane & 7);
    const int bKb  = ((lane >> 3) & 1) * 16;

    load_chunk(0, 0);

    for (int j = 0; j < nch; j++) {
        __syncthreads();
        if (j + 1 < nch) {
            load_chunk(j + 1, (j + 1) & 1);
            asm volatile("cp.async.wait_group 1;" ::: "memory");
        } else {
            asm volatile("cp.async.wait_group 0;" ::: "memory");
        }
        __syncthreads();

        const uint32_t stage = sb + (j & 1) * STAGE_BYTES;

        #pragma unroll
        for (int ks = 0; ks < 4; ks++) {
            const int kbyte = ks * 32;
            uint32_t ah[4][4], al[4][4];
            #pragma unroll
            for (int mf = 0; mf < 4; mf++) {
                const uint32_t off = SW128((aRow + mf * 16) * 128 + kbyte + aKb);
                LDMX4(ah[mf][0], ah[mf][1], ah[mf][2], ah[mf][3],
                      stage + S_A_HI + off);
                LDMX4(al[mf][0], al[mf][1], al[mf][2], al[mf][3],
                      stage + S_A_LO + off);
            }
            #pragma unroll
            for (int np = 0; np < 4; np++) {
                const uint32_t off = SW128((bRowBase + np * 16) * 128 + kbyte + bKb);
                uint32_t h0, h1, h2r, h3, l0, l1, l2, l3;
                LDMX4(h0, h1, h2r, h3, stage + S_B_HI + off);
                LDMX4(l0, l1, l2, l3, stage + S_B_LO + off);
                #pragma unroll
                for (int mf = 0; mf < 4; mf++) {
                    MMA16816(acc[mf][2 * np],     ah[mf][0], ah[mf][1], ah[mf][2], ah[mf][3], h0, h1);
                    MMA16816(acc[mf][2 * np],     ah[mf][0], ah[mf][1], ah[mf][2], ah[mf][3], l0, l1);
                    MMA16816(acc[mf][2 * np],     al[mf][0], al[mf][1], al[mf][2], al[mf][3], h0, h1);
                    MMA16816(acc[mf][2 * np + 1], ah[mf][0], ah[mf][1], ah[mf][2], ah[mf][3], h2r, h3);
                    MMA16816(acc[mf][2 * np + 1], ah[mf][0], ah[mf][1], ah[mf][2], ah[mf][3], l2, l3);
                    MMA16816(acc[mf][2 * np + 1], al[mf][0], al[mf][1], al[mf][2], al[mf][3], h2r, h3);
                }
            }
        }
    }

    // ---- epilogue ----
    if (mode) {
        // bias + relu -> split bf16 h1
        #pragma unroll
        for (int mf = 0; mf < 4; mf++) {
            const int r0 = rowA0 + warpM * 64 + mf * 16 + g;
            const int r1 = r0 + 8;
            #pragma unroll
            for (int nf = 0; nf < 8; nf++) {
                const int col = colB0 + warpN * 64 + nf * 8 + tig * 2;
                const float bx = __ldg(bias + col);
                const float by = __ldg(bias + col + 1);
                float v0x = fmaxf(acc[mf][nf][0] + bx, 0.0f);
                float v0y = fmaxf(acc[mf][nf][1] + by, 0.0f);
                float v1x = fmaxf(acc[mf][nf][2] + bx, 0.0f);
                float v1y = fmaxf(acc[mf][nf][3] + by, 0.0f);
                __nv_bfloat162 h0, l0, h1, l1;
                h0.x = __float2bfloat16(v0x);
                h0.y = __float2bfloat16(v0y);
                l0.x = __float2bfloat16(v0x - __bfloat162float(h0.x));
                l0.y = __float2bfloat16(v0y - __bfloat162float(h0.y));
                h1.x = __float2bfloat16(v1x);
                h1.y = __float2bfloat16(v1y);
                l1.x = __float2bfloat16(v1x - __bfloat162float(h1.x));
                l1.y = __float2bfloat16(v1y - __bfloat162float(h1.y));
                *(__nv_bfloat162*)(outHi + (size_t)r0 * Npitch + col) = h0;
                *(__nv_bfloat162*)(outLo + (size_t)r0 * Npitch + col) = l0;
                *(__nv_bfloat162*)(outHi + (size_t)r1 * Npitch + col) = h1;
                *(__nv_bfloat162*)(outLo + (size_t)r1 * Npitch + col) = l1;
            }
        }
    } else {
        // fused GEMV: scores[row] += sum_col relu(h2[row,col]) * w3[col]
        #pragma unroll
        for (int mf = 0; mf < 4; mf++) {
            const int r0 = rowA0 + warpM * 64 + mf * 16 + g;
            const int r1 = r0 + 8;
            float p0 = 0.0f, p1 = 0.0f;
            #pragma unroll
            for (int nf = 0; nf < 8; nf++) {
                const int col = colB0 + warpN * 64 + nf * 8 + tig * 2;
                const float bx = __ldg(bias + col);
                const float by = __ldg(bias + col + 1);
                const float wx = __ldg(w3 + col);
                const float wy = __ldg(w3 + col + 1);
                p0 += fmaxf(acc[mf][nf][0] + bx, 0.0f) * wx
                    + fmaxf(acc[mf][nf][1] + by, 0.0f) * wy;
                p1 += fmaxf(acc[mf][nf][2] + bx, 0.0f) * wx
                    + fmaxf(acc[mf][nf][3] + by, 0.0f) * wy;
            }
            // reduce over the 4 tig lanes (same g => same rows)
            p0 += __shfl_xor_sync(0xffffffffu, p0, 1);
            p0 += __shfl_xor_sync(0xffffffffu, p0, 2);
            p1 += __shfl_xor_sync(0xffffffffu, p1, 1);
            p1 += __shfl_xor_sync(0xffffffffu, p1, 2);
            if (tig == 0) {
                atomicAdd(scores + r0, p0);
                atomicAdd(scores + r1, p1);
            }
        }
    }
}

// ---------------------------------------------------------------------------
// soft_rank (parallel PAV). b3 is folded in here: ranks are shift-invariant,
// and the scores output must include it.
// ---------------------------------------------------------------------------
__device__ __forceinline__ int pav_merge(int Lbase, int nl, int Rbase, int nr,
                                         int* __restrict__ pst,
                                         int* __restrict__ pcn,
                                         float* __restrict__ psm)
{
    int len = nl;
    for (int t = 0; t < nr; t++) {
        int   cs = pst[Rbase + t];
        int   cc = pcn[Rbase + t];
        float cm = psm[Rbase + t];
        while (len > 0) {
            float ts = psm[Lbase + len - 1];
            int   tc = pcn[Lbase + len - 1];
            if (ts * (float)cc < cm * (float)tc) {
                cm += ts; cc += tc; cs = pst[Lbase + len - 1];
                len--;
            } else break;
        }
        pst[Lbase + len] = cs;
        pcn[Lbase + len] = cc;
        psm[Lbase + len] = cm;
        len++;
    }
    return len;
}

__global__ void softrank_kernel(const float* __restrict__ scores,
                                const float* __restrict__ b3,
                                float* __restrict__ out,
                                int n)
{
    extern __shared__ float smf[];
    float* s   = smf;
    float* psm = s + n;
    int*   idx = (int*)(psm + n);
    int*   pst = idx + n;
    int*   pcn = pst + n;
    int*   cA  = pcn + n;
    int*   cB  = cA + n / 2;

    const int tid = threadIdx.x;
    const int nt  = blockDim.x;
    const float b3v = b3[0];

    for (int i = tid; i < n; i += nt) { s[i] = scores[i] + b3v; idx[i] = i; }
    __syncthreads();

    for (int k = 2; k <= n; k <<= 1) {
        for (int j = k >> 1; j > 0; j >>= 1) {
            for (int i = tid; i < n; i += nt) {
                int ixj = i ^ j;
                if (ixj > i) {
                    bool up = ((i & k) == 0);
                    float a = s[i], b = s[ixj];
                    bool sw = up ? (a < b) : (a > b);
                    if (sw) {
                        s[i] = b; s[ixj] = a;
                        int t = idx[i]; idx[i] = idx[ixj]; idx[ixj] = t;
                    }
                }
            }
            __syncthreads();
        }
    }

    for (int i = tid; i < n; i += nt) {
        pst[i] = i;
        pcn[i] = 1;
        psm[i] = s[i] - (float)(n - i);
    }
    __syncthreads();

    for (int g2 = tid; g2 < n / 2; g2 += nt)
        cA[g2] = pav_merge(2 * g2, 1, 2 * g2 + 1, 1, pst, pcn, psm);
    __syncthreads();

    int* cCur = cA;
    int* cNxt = cB;
    for (int L = 2; (1 << L) <= n; L++) {
        const int half = 1 << (L - 1);
        const int nm = n >> L;
        for (int g2 = tid; g2 < nm; g2 += nt)
            cNxt[g2] = pav_merge((g2 << L), cCur[2 * g2],
                                 (g2 << L) + half, cCur[2 * g2 + 1],
                                 pst, pcn, psm);
        __syncthreads();
        int* t = cCur; cCur = cNxt; cNxt = t;
    }
    const int P = cCur[0];

    for (int i = tid; i < n; i += nt) {
        int lo = 0, hi = P - 1;
        while (lo < hi) {
            int mid = (lo + hi + 1) >> 1;
            if (pst[mid] <= i) lo = mid; else hi = mid - 1;
        }
        float dual = psm[lo] / (float)pcn[lo];
        out[idx[i]] = s[i] - dual;      // rank, original order
        out[n + i]  = scores[i] + b3v;  // scores (with bias)
    }
}

// ---------------------------------------------------------------------------
// Launch
// ---------------------------------------------------------------------------
extern "C" void kernel_launch(void* const* d_in, const int* in_sizes, int n_in,
                              void* d_out, int out_size)
{
    const float* x  = (const float*)d_in[0];
    const float* W1 = (const float*)d_in[1];
    const float* b1 = (const float*)d_in[2];
    const float* W2 = (const float*)d_in[3];
    const float* b2 = (const float*)d_in[4];
    const float* W3 = (const float*)d_in[5];
    const float* b3 = (const float*)d_in[6];
    float* out = (float*)d_out;

    __nv_bfloat16 *xhi, *xlo, *w1hi, *w1lo, *w2hi, *w2lo, *h1hi, *h1lo;
    float *sc;
    cudaGetSymbolAddress((void**)&xhi,  g_xhi);
    cudaGetSymbolAddress((void**)&xlo,  g_xlo);
    cudaGetSymbolAddress((void**)&w1hi, g_w1hi);
    cudaGetSymbolAddress((void**)&w1lo, g_w1lo);
    cudaGetSymbolAddress((void**)&w2hi, g_w2hi);
    cudaGetSymbolAddress((void**)&w2lo, g_w2lo);
    cudaGetSymbolAddress((void**)&h1hi, g_h1hi);
    cudaGetSymbolAddress((void**)&h1lo, g_h1lo);
    cudaGetSymbolAddress((void**)&sc,   g_scores);

    // conversions
    {
        int n = MB * DIN;
        split_rows<<<(n / 4 + 255) / 256, 256>>>(x, xhi, xlo, n);
        transpose_split64<<<dim3(HID / 32, DIN / 64), dim3(32, 8)>>>(W1, w1hi, w1lo, DIN, HID);
        transpose_split64<<<dim3(HID / 32, HID / 64), dim3(32, 8)>>>(W2, w2hi, w2lo, HID, HID);
    }

    cudaFuncSetAttribute(gemm_mma,
                         cudaFuncAttributeMaxDynamicSharedMemorySize, GEMM_SMEM);

    // layer 1: relu(x @ W1 + b1) -> h1 (split bf16)
    {
        dim3 grid(HID / BN, MB / BM);
        gemm_mma<<<grid, 256, GEMM_SMEM>>>(xhi, xlo, w1hi, w1lo, b1,
                                           DIN, HID, 1,
                                           h1hi, h1lo, nullptr, nullptr);
    }
    // layer 2 + fused GEMV: scores = relu(h1 @ W2 + b2) @ W3
    zero_scores<<<MB / 1024, 1024>>>(sc);
    {
        dim3 grid(HID / BN, MB / BM);
        gemm_mma<<<grid, 256, GEMM_SMEM>>>(h1hi, h1lo, w2hi, w2lo, b2,
                                           HID, HID, 0,
                                           nullptr, nullptr, W3, sc);
    }
    // soft_rank (+ b3)
    {
        size_t smem = (size_t)MB * 6 * sizeof(float);
        cudaFuncSetAttribute(softrank_kernel,
                             cudaFuncAttributeMaxDynamicSharedMemorySize,
                             (int)smem);
        softrank_kernel<<<1, 1024, smem>>>(sc, b3, out, MB);
    }
}

// round 11
// speedup vs baseline: 3.8479x; 1.3174x over previous
#include <cuda_runtime.h>
#include <cuda_fp16.h>
#include <cstdint>

// ---------------------------------------------------------------------------
// Shapes (fixed by the dataset)
// ---------------------------------------------------------------------------
#define MB   4096
#define DIN  512
#define HID  2048

// ---------------------------------------------------------------------------
// Device scratch: A-side split fp16 (hi+lo), B-side single fp16
// ---------------------------------------------------------------------------
__device__ __half g_xhi[(size_t)MB * DIN],  g_xlo[(size_t)MB * DIN];
__device__ __half g_w1[(size_t)HID * DIN];
__device__ __half g_w2[(size_t)HID * HID];
__device__ __half g_h1hi[(size_t)MB * HID], g_h1lo[(size_t)MB * HID];
__device__ float g_scores[MB];

// ---------------------------------------------------------------------------
// Helpers
// ---------------------------------------------------------------------------
__device__ __forceinline__ uint32_t smem_u32(const void* p) {
    uint32_t a;
    asm("{ .reg .u64 t; cvta.to.shared.u64 t, %1; cvt.u32.u64 %0, t; }"
        : "=r"(a) : "l"(p));
    return a;
}

#define SW128(o) ((o) ^ (((o) >> 3) & 0x70))

#define CPA16(smem, gptr) \
    asm volatile("cp.async.cg.shared.global [%0], [%1], 16;" \
                 :: "r"(smem), "l"(gptr))

#define LDMX4(r0, r1, r2, r3, addr) \
    asm volatile("ldmatrix.sync.aligned.m8n8.x4.shared.b16 {%0,%1,%2,%3}, [%4];" \
                 : "=r"(r0), "=r"(r1), "=r"(r2), "=r"(r3) : "r"(addr))

#define MMAF16(c, a0, a1, a2, a3, b0, b1) \
    asm volatile("mma.sync.aligned.m16n8k16.row.col.f32.f16.f16.f32 " \
                 "{%0,%1,%2,%3}, {%4,%5,%6,%7}, {%8,%9}, {%0,%1,%2,%3};" \
                 : "+f"((c)[0]), "+f"((c)[1]), "+f"((c)[2]), "+f"((c)[3]) \
                 : "r"(a0), "r"(a1), "r"(a2), "r"(a3), "r"(b0), "r"(b1))

// ---------------------------------------------------------------------------
// Conversions
// ---------------------------------------------------------------------------
// fp32 rows -> fp16 (hi, lo) split
__global__ void split_rows_h(const float* __restrict__ in,
                             __half* __restrict__ hi,
                             __half* __restrict__ lo, int n)
{
    int i = (blockIdx.x * blockDim.x + threadIdx.x) * 4;
    if (i >= n) return;
    float4 v = *(const float4*)(in + i);
    float vv[4] = {v.x, v.y, v.z, v.w};
    #pragma unroll
    for (int k = 0; k < 4; k++) {
        __half h = __float2half_rn(vv[k]);
        hi[i + k] = h;
        lo[i + k] = __float2half_rn(vv[k] - __half2float(h));
    }
}

// W [K,N] row-major -> T [N,K] single fp16, 64-wide k tiles
// grid (N/32, K/64), block (32,8)
__global__ void transpose_h64(const float* __restrict__ W,
                              __half* __restrict__ T, int K, int N)
{
    __shared__ float t[64][33];
    const int n0 = blockIdx.x * 32, k0 = blockIdx.y * 64;
    const int tx = threadIdx.x, ty = threadIdx.y;
    #pragma unroll
    for (int r = ty; r < 64; r += 8)
        t[r][tx] = W[(size_t)(k0 + r) * N + n0 + tx];
    __syncthreads();
    #pragma unroll
    for (int nr = ty; nr < 32; nr += 8) {
        __half2 h;
        h.x = __float2half_rn(t[tx * 2][nr]);
        h.y = __float2half_rn(t[tx * 2 + 1][nr]);
        *(__half2*)(T + (size_t)(n0 + nr) * K + k0 + tx * 2) = h;
    }
}

__global__ void zero_scores(float* __restrict__ s)
{
    s[blockIdx.x * 1024 + threadIdx.x] = 0.0f;
}

// ---------------------------------------------------------------------------
// fp16 2-product GEMM: D = relu((Ahi+Alo) @ B^T + bias)
// A hi/lo [M,K] fp16 K-major; B [N,K] fp16 K-major (single).
// CTA 128x256, 256 threads, warp grid 2x4, warp tile 64x64, KC=64, 2-stage.
// mode=1: write split fp16 h1.  mode=0: fused GEMV into scores.
// ---------------------------------------------------------------------------
#define BM 128
#define BN 256
#define KC 64
#define S_A_HI 0
#define S_A_LO 16384
#define S_B    32768
#define STAGE_BYTES 65536          // A 2x16K + B 32K
#define GEMM_SMEM (2 * STAGE_BYTES)   // 131072

__global__ __launch_bounds__(256, 1)
void gemm_mma(const __half* __restrict__ Ahi,
              const __half* __restrict__ Alo,
              const __half* __restrict__ B,
              const float* __restrict__ bias,
              int K, int Npitch, int mode,
              __half* __restrict__ outHi,
              __half* __restrict__ outLo,
              const float* __restrict__ w3,
              float* __restrict__ scores)
{
    extern __shared__ char smem[];
    const uint32_t sb = smem_u32(smem);

    const int tid   = threadIdx.x;
    const int lane  = tid & 31;
    const int w     = tid >> 5;
    const int warpM = w >> 2;          // 0..1 (64 rows)
    const int warpN = w & 3;           // 0..3 (64 cols)
    const int g     = lane >> 2;
    const int tig   = lane & 3;

    const int rowA0 = blockIdx.y * BM;
    const int colB0 = blockIdx.x * BN;
    const int nch   = K / KC;

    float acc[4][8][4];
    #pragma unroll
    for (int mf = 0; mf < 4; mf++)
        #pragma unroll
        for (int nf = 0; nf < 8; nf++)
            #pragma unroll
            for (int e = 0; e < 4; e++)
                acc[mf][nf][e] = 0.0f;

    auto load_chunk = [&](int j, int st) {
        const uint32_t stage = sb + st * STAGE_BYTES;
        const size_t cOff = (size_t)j * KC;
        // A tiles: 128 rows x 8 segs x {hi,lo} = 2048 segs
        #pragma unroll
        for (int u = 0; u < 8; u++) {
            const int seg = u * 256 + tid;
            const int r = seg >> 4;
            const int halfsel = (seg >> 3) & 1;
            const int s = (seg & 7) << 4;
            const uint32_t sw = SW128(r * 128 + s);
            const __half* base = halfsel ? Alo : Ahi;
            const char* gp = (const char*)(base + (size_t)(rowA0 + r) * K + cOff) + s;
            CPA16(stage + (halfsel ? S_A_LO : S_A_HI) + sw, gp);
        }
        // B tile: 256 rows x 8 segs = 2048 segs
        #pragma unroll
        for (int u = 0; u < 8; u++) {
            const int seg = u * 256 + tid;
            const int r = seg >> 3;
            const int s = (seg & 7) << 4;
            const uint32_t sw = SW128(r * 128 + s);
            const char* gp = (const char*)(B + (size_t)(colB0 + r) * K + cOff) + s;
            CPA16(stage + S_B + sw, gp);
        }
        asm volatile("cp.async.commit_group;");
    };

    const int aRow = warpM * 64 + (lane & 7) + ((lane >> 3) & 1) * 8;
    const int aKb  = ((lane >> 4) & 1) * 16;
    const int bRowBase = warpN * 64 + ((lane >> 4) & 1) * 8 + (lane & 7);
    const int bKb  = ((lane >> 3) & 1) * 16;

    load_chunk(0, 0);

    for (int j = 0; j < nch; j++) {
        __syncthreads();
        if (j + 1 < nch) {
            load_chunk(j + 1, (j + 1) & 1);
            asm volatile("cp.async.wait_group 1;" ::: "memory");
        } else {
            asm volatile("cp.async.wait_group 0;" ::: "memory");
        }
        __syncthreads();

        const uint32_t stage = sb + (j & 1) * STAGE_BYTES;

        #pragma unroll
        for (int ks = 0; ks < 4; ks++) {
            const int kbyte = ks * 32;
            uint32_t ah[4][4], al[4][4];
            #pragma unroll
            for (int mf = 0; mf < 4; mf++) {
                const uint32_t off = SW128((aRow + mf * 16) * 128 + kbyte + aKb);
                LDMX4(ah[mf][0], ah[mf][1], ah[mf][2], ah[mf][3],
                      stage + S_A_HI + off);
                LDMX4(al[mf][0], al[mf][1], al[mf][2], al[mf][3],
                      stage + S_A_LO + off);
            }
            #pragma unroll
            for (int np = 0; np < 4; np++) {
                const uint32_t off = SW128((bRowBase + np * 16) * 128 + kbyte + bKb);
                uint32_t b0, b1, b2, b3r;
                LDMX4(b0, b1, b2, b3r, stage + S_B + off);
                #pragma unroll
                for (int mf = 0; mf < 4; mf++) {
                    MMAF16(acc[mf][2 * np],     ah[mf][0], ah[mf][1], ah[mf][2], ah[mf][3], b0, b1);
                    MMAF16(acc[mf][2 * np],     al[mf][0], al[mf][1], al[mf][2], al[mf][3], b0, b1);
                    MMAF16(acc[mf][2 * np + 1], ah[mf][0], ah[mf][1], ah[mf][2], ah[mf][3], b2, b3r);
                    MMAF16(acc[mf][2 * np + 1], al[mf][0], al[mf][1], al[mf][2], al[mf][3], b2, b3r);
                }
            }
        }
    }

    // ---- epilogue ----
    if (mode) {
        // bias + relu -> split fp16 h1
        #pragma unroll
        for (int mf = 0; mf < 4; mf++) {
            const int r0 = rowA0 + warpM * 64 + mf * 16 + g;
            const int r1 = r0 + 8;
            #pragma unroll
            for (int nf = 0; nf < 8; nf++) {
                const int col = colB0 + warpN * 64 + nf * 8 + tig * 2;
                const float bx = __ldg(bias + col);
                const float by = __ldg(bias + col + 1);
                float v0x = fmaxf(acc[mf][nf][0] + bx, 0.0f);
                float v0y = fmaxf(acc[mf][nf][1] + by, 0.0f);
                float v1x = fmaxf(acc[mf][nf][2] + bx, 0.0f);
                float v1y = fmaxf(acc[mf][nf][3] + by, 0.0f);
                __half2 h0, l0, h1, l1;
                h0.x = __float2half_rn(v0x);
                h0.y = __float2half_rn(v0y);
                l0.x = __float2half_rn(v0x - __half2float(h0.x));
                l0.y = __float2half_rn(v0y - __half2float(h0.y));
                h1.x = __float2half_rn(v1x);
                h1.y = __float2half_rn(v1y);
                l1.x = __float2half_rn(v1x - __half2float(h1.x));
                l1.y = __float2half_rn(v1y - __half2float(h1.y));
                *(__half2*)(outHi + (size_t)r0 * Npitch + col) = h0;
                *(__half2*)(outLo + (size_t)r0 * Npitch + col) = l0;
                *(__half2*)(outHi + (size_t)r1 * Npitch + col) = h1;
                *(__half2*)(outLo + (size_t)r1 * Npitch + col) = l1;
            }
        }
    } else {
        // fused GEMV: scores[row] += sum_col relu(h2[row,col]) * w3[col]
        #pragma unroll
        for (int mf = 0; mf < 4; mf++) {
            const int r0 = rowA0 + warpM * 64 + mf * 16 + g;
            const int r1 = r0 + 8;
            float p0 = 0.0f, p1 = 0.0f;
            #pragma unroll
            for (int nf = 0; nf < 8; nf++) {
                const int col = colB0 + warpN * 64 + nf * 8 + tig * 2;
                const float bx = __ldg(bias + col);
                const float by = __ldg(bias + col + 1);
                const float wx = __ldg(w3 + col);
                const float wy = __ldg(w3 + col + 1);
                p0 += fmaxf(acc[mf][nf][0] + bx, 0.0f) * wx
                    + fmaxf(acc[mf][nf][1] + by, 0.0f) * wy;
                p1 += fmaxf(acc[mf][nf][2] + bx, 0.0f) * wx
                    + fmaxf(acc[mf][nf][3] + by, 0.0f) * wy;
            }
            p0 += __shfl_xor_sync(0xffffffffu, p0, 1);
            p0 += __shfl_xor_sync(0xffffffffu, p0, 2);
            p1 += __shfl_xor_sync(0xffffffffu, p1, 1);
            p1 += __shfl_xor_sync(0xffffffffu, p1, 2);
            if (tig == 0) {
                atomicAdd(scores + r0, p0);
                atomicAdd(scores + r1, p1);
            }
        }
    }
}

// ---------------------------------------------------------------------------
// soft_rank (parallel PAV), b3 folded in (rank shift-invariance)
// ---------------------------------------------------------------------------
__device__ __forceinline__ int pav_merge(int Lbase, int nl, int Rbase, int nr,
                                         int* __restrict__ pst,
                                         int* __restrict__ pcn,
                                         float* __restrict__ psm)
{
    int len = nl;
    for (int t = 0; t < nr; t++) {
        int   cs = pst[Rbase + t];
        int   cc = pcn[Rbase + t];
        float cm = psm[Rbase + t];
        while (len > 0) {
            float ts = psm[Lbase + len - 1];
            int   tc = pcn[Lbase + len - 1];
            if (ts * (float)cc < cm * (float)tc) {
                cm += ts; cc += tc; cs = pst[Lbase + len - 1];
                len--;
            } else break;
        }
        pst[Lbase + len] = cs;
        pcn[Lbase + len] = cc;
        psm[Lbase + len] = cm;
        len++;
    }
    return len;
}

__global__ void softrank_kernel(const float* __restrict__ scores,
                                const float* __restrict__ b3,
                                float* __restrict__ out,
                                int n)
{
    extern __shared__ float smf[];
    float* s   = smf;
    float* psm = s + n;
    int*   idx = (int*)(psm + n);
    int*   pst = idx + n;
    int*   pcn = pst + n;
    int*   cA  = pcn + n;
    int*   cB  = cA + n / 2;

    const int tid = threadIdx.x;
    const int nt  = blockDim.x;
    const float b3v = b3[0];

    for (int i = tid; i < n; i += nt) { s[i] = scores[i] + b3v; idx[i] = i; }
    __syncthreads();

    for (int k = 2; k <= n; k <<= 1) {
        for (int j = k >> 1; j > 0; j >>= 1) {
            for (int i = tid; i < n; i += nt) {
                int ixj = i ^ j;
                if (ixj > i) {
                    bool up = ((i & k) == 0);
                    float a = s[i], b = s[ixj];
                    bool sw = up ? (a < b) : (a > b);
                    if (sw) {
                        s[i] = b; s[ixj] = a;
                        int t = idx[i]; idx[i] = idx[ixj]; idx[ixj] = t;
                    }
                }
            }
            __syncthreads();
        }
    }

    for (int i = tid; i < n; i += nt) {
        pst[i] = i;
        pcn[i] = 1;
        psm[i] = s[i] - (float)(n - i);
    }
    __syncthreads();

    for (int g2 = tid; g2 < n / 2; g2 += nt)
        cA[g2] = pav_merge(2 * g2, 1, 2 * g2 + 1, 1, pst, pcn, psm);
    __syncthreads();

    int* cCur = cA;
    int* cNxt = cB;
    for (int L = 2; (1 << L) <= n; L++) {
        const int half = 1 << (L - 1);
        const int nm = n >> L;
        for (int g2 = tid; g2 < nm; g2 += nt)
            cNxt[g2] = pav_merge((g2 << L), cCur[2 * g2],
                                 (g2 << L) + half, cCur[2 * g2 + 1],
                                 pst, pcn, psm);
        __syncthreads();
        int* t = cCur; cCur = cNxt; cNxt = t;
    }
    const int P = cCur[0];

    for (int i = tid; i < n; i += nt) {
        int lo = 0, hi = P - 1;
        while (lo < hi) {
            int mid = (lo + hi + 1) >> 1;
            if (pst[mid] <= i) lo = mid; else hi = mid - 1;
        }
        float dual = psm[lo] / (float)pcn[lo];
        out[idx[i]] = s[i] - dual;      // rank, original order
        out[n + i]  = scores[i] + b3v;  // scores (with bias)
    }
}

// ---------------------------------------------------------------------------
// Launch
// ---------------------------------------------------------------------------
extern "C" void kernel_launch(void* const* d_in, const int* in_sizes, int n_in,
                              void* d_out, int out_size)
{
    const float* x  = (const float*)d_in[0];
    const float* W1 = (const float*)d_in[1];
    const float* b1 = (const float*)d_in[2];
    const float* W2 = (const float*)d_in[3];
    const float* b2 = (const float*)d_in[4];
    const float* W3 = (const float*)d_in[5];
    const float* b3 = (const float*)d_in[6];
    float* out = (float*)d_out;

    __half *xhi, *xlo, *w1, *w2, *h1hi, *h1lo;
    float *sc;
    cudaGetSymbolAddress((void**)&xhi,  g_xhi);
    cudaGetSymbolAddress((void**)&xlo,  g_xlo);
    cudaGetSymbolAddress((void**)&w1,   g_w1);
    cudaGetSymbolAddress((void**)&w2,   g_w2);
    cudaGetSymbolAddress((void**)&h1hi, g_h1hi);
    cudaGetSymbolAddress((void**)&h1lo, g_h1lo);
    cudaGetSymbolAddress((void**)&sc,   g_scores);

    // conversions
    {
        int n = MB * DIN;
        split_rows_h<<<(n / 4 + 255) / 256, 256>>>(x, xhi, xlo, n);
        transpose_h64<<<dim3(HID / 32, DIN / 64), dim3(32, 8)>>>(W1, w1, DIN, HID);
        transpose_h64<<<dim3(HID / 32, HID / 64), dim3(32, 8)>>>(W2, w2, HID, HID);
    }

    cudaFuncSetAttribute(gemm_mma,
                         cudaFuncAttributeMaxDynamicSharedMemorySize, GEMM_SMEM);

    // layer 1: relu(x @ W1 + b1) -> h1 (split fp16)
    {
        dim3 grid(HID / BN, MB / BM);
        gemm_mma<<<grid, 256, GEMM_SMEM>>>(xhi, xlo, w1, b1,
                                           DIN, HID, 1,
                                           h1hi, h1lo, nullptr, nullptr);
    }
    // layer 2 + fused GEMV: scores = relu(h1 @ W2 + b2) @ W3
    zero_scores<<<MB / 1024, 1024>>>(sc);
    {
        dim3 grid(HID / BN, MB / BM);
        gemm_mma<<<grid, 256, GEMM_SMEM>>>(h1hi, h1lo, w2, b2,
                                           HID, HID, 0,
                                           nullptr, nullptr, W3, sc);
    }
    // soft_rank (+ b3)
    {
        size_t smem = (size_t)MB * 6 * sizeof(float);
        cudaFuncSetAttribute(softrank_kernel,
                             cudaFuncAttributeMaxDynamicSharedMemorySize,
                             (int)smem);
        softrank_kernel<<<1, 1024, smem>>>(sc, b3, out, MB);
    }
}

// round 12
// speedup vs baseline: 5.3473x; 1.3897x over previous
#include <cuda_runtime.h>
#include <cuda_fp16.h>
#include <cstdint>

// ---------------------------------------------------------------------------
// Shapes (fixed by the dataset)
// ---------------------------------------------------------------------------
#define MB   4096
#define DIN  512
#define HID  2048

// ---------------------------------------------------------------------------
// Device scratch
// ---------------------------------------------------------------------------
__device__ __half g_xhi[(size_t)MB * DIN], g_xlo[(size_t)MB * DIN];
__device__ __half g_w1[(size_t)HID * DIN];
__device__ __half g_w2[(size_t)HID * HID];
__device__ __half g_h1[(size_t)MB * HID];
__device__ float g_scores[MB];

// ---------------------------------------------------------------------------
// Helpers
// ---------------------------------------------------------------------------
__device__ __forceinline__ uint32_t smem_u32(const void* p) {
    uint32_t a;
    asm("{ .reg .u64 t; cvta.to.shared.u64 t, %1; cvt.u32.u64 %0, t; }"
        : "=r"(a) : "l"(p));
    return a;
}

#define SW128(o) ((o) ^ (((o) >> 3) & 0x70))

#define CPA16(smem, gptr) \
    asm volatile("cp.async.cg.shared.global [%0], [%1], 16;" \
                 :: "r"(smem), "l"(gptr))

#define LDMX4(r0, r1, r2, r3, addr) \
    asm volatile("ldmatrix.sync.aligned.m8n8.x4.shared.b16 {%0,%1,%2,%3}, [%4];" \
                 : "=r"(r0), "=r"(r1), "=r"(r2), "=r"(r3) : "r"(addr))

#define MMAF16(c, a0, a1, a2, a3, b0, b1) \
    asm volatile("mma.sync.aligned.m16n8k16.row.col.f32.f16.f16.f32 " \
                 "{%0,%1,%2,%3}, {%4,%5,%6,%7}, {%8,%9}, {%0,%1,%2,%3};" \
                 : "+f"((c)[0]), "+f"((c)[1]), "+f"((c)[2]), "+f"((c)[3]) \
                 : "r"(a0), "r"(a1), "r"(a2), "r"(a3), "r"(b0), "r"(b1))

// ---------------------------------------------------------------------------
// Conversions
// ---------------------------------------------------------------------------
__global__ void split_rows_h(const float* __restrict__ in,
                             __half* __restrict__ hi,
                             __half* __restrict__ lo, int n)
{
    int i = (blockIdx.x * blockDim.x + threadIdx.x) * 4;
    if (i >= n) return;
    float4 v = *(const float4*)(in + i);
    float vv[4] = {v.x, v.y, v.z, v.w};
    #pragma unroll
    for (int k = 0; k < 4; k++) {
        __half h = __float2half_rn(vv[k]);
        hi[i + k] = h;
        lo[i + k] = __float2half_rn(vv[k] - __half2float(h));
    }
}

// W [K,N] row-major -> T [N,K] single fp16, 64-wide k tiles
__global__ void transpose_h64(const float* __restrict__ W,
                              __half* __restrict__ T, int K, int N)
{
    __shared__ float t[64][33];
    const int n0 = blockIdx.x * 32, k0 = blockIdx.y * 64;
    const int tx = threadIdx.x, ty = threadIdx.y;
    #pragma unroll
    for (int r = ty; r < 64; r += 8)
        t[r][tx] = W[(size_t)(k0 + r) * N + n0 + tx];
    __syncthreads();
    #pragma unroll
    for (int nr = ty; nr < 32; nr += 8) {
        __half2 h;
        h.x = __float2half_rn(t[tx * 2][nr]);
        h.y = __float2half_rn(t[tx * 2 + 1][nr]);
        *(__half2*)(T + (size_t)(n0 + nr) * K + k0 + tx * 2) = h;
    }
}

__global__ void zero_scores(float* __restrict__ s)
{
    s[blockIdx.x * 1024 + threadIdx.x] = 0.0f;
}

// ---------------------------------------------------------------------------
// fp16 GEMM, NPROD products on the A side (1 = single, 2 = hi+lo split).
// D = relu(A @ B^T + bias).  A [M,K] fp16 K-major (hi[,lo]); B [N,K] fp16.
// CTA 128x256, 256 threads, warp grid 2x4, warp tile 64x64, KC=64, 2-stage.
// MODE=1: write single fp16 h1.  MODE=0: fused GEMV into scores.
// ---------------------------------------------------------------------------
#define BM 128
#define BN 256
#define KC 64
#define S_A_HI 0
#define S_A_LO 16384
#define S_B    32768
#define STAGE_BYTES 65536
#define GEMM_SMEM (2 * STAGE_BYTES)   // 131072

template<int NPROD, int MODE>
__global__ __launch_bounds__(256, 1)
void gemm_mma(const __half* __restrict__ Ahi,
              const __half* __restrict__ Alo,
              const __half* __restrict__ B,
              const float* __restrict__ bias,
              int K, int Npitch,
              __half* __restrict__ outH,
              const float* __restrict__ w3,
              float* __restrict__ scores)
{
    extern __shared__ char smem[];
    const uint32_t sb = smem_u32(smem);

    const int tid   = threadIdx.x;
    const int lane  = tid & 31;
    const int w     = tid >> 5;
    const int warpM = w >> 2;          // 0..1 (64 rows)
    const int warpN = w & 3;           // 0..3 (64 cols)
    const int g     = lane >> 2;
    const int tig   = lane & 3;

    const int rowA0 = blockIdx.y * BM;
    const int colB0 = blockIdx.x * BN;
    const int nch   = K / KC;

    float acc[4][8][4];
    #pragma unroll
    for (int mf = 0; mf < 4; mf++)
        #pragma unroll
        for (int nf = 0; nf < 8; nf++)
            #pragma unroll
            for (int e = 0; e < 4; e++)
                acc[mf][nf][e] = 0.0f;

    auto load_chunk = [&](int j, int st) {
        const uint32_t stage = sb + st * STAGE_BYTES;
        const size_t cOff = (size_t)j * KC;
        // A hi tile: 1024 segs
        #pragma unroll
        for (int u = 0; u < 4; u++) {
            const int seg = u * 256 + tid;
            const int r = seg >> 3;
            const int s = (seg & 7) << 4;
            const uint32_t sw = SW128(r * 128 + s);
            const char* gp = (const char*)(Ahi + (size_t)(rowA0 + r) * K + cOff) + s;
            CPA16(stage + S_A_HI + sw, gp);
        }
        if constexpr (NPROD == 2) {
            #pragma unroll
            for (int u = 0; u < 4; u++) {
                const int seg = u * 256 + tid;
                const int r = seg >> 3;
                const int s = (seg & 7) << 4;
                const uint32_t sw = SW128(r * 128 + s);
                const char* gp = (const char*)(Alo + (size_t)(rowA0 + r) * K + cOff) + s;
                CPA16(stage + S_A_LO + sw, gp);
            }
        }
        // B tile: 2048 segs
        #pragma unroll
        for (int u = 0; u < 8; u++) {
            const int seg = u * 256 + tid;
            const int r = seg >> 3;
            const int s = (seg & 7) << 4;
            const uint32_t sw = SW128(r * 128 + s);
            const char* gp = (const char*)(B + (size_t)(colB0 + r) * K + cOff) + s;
            CPA16(stage + S_B + sw, gp);
        }
        asm volatile("cp.async.commit_group;");
    };

    const int aRow = warpM * 64 + (lane & 7) + ((lane >> 3) & 1) * 8;
    const int aKb  = ((lane >> 4) & 1) * 16;
    const int bRowBase = warpN * 64 + ((lane >> 4) & 1) * 8 + (lane & 7);
    const int bKb  = ((lane >> 3) & 1) * 16;

    load_chunk(0, 0);

    for (int j = 0; j < nch; j++) {
        __syncthreads();
        if (j + 1 < nch) {
            load_chunk(j + 1, (j + 1) & 1);
            asm volatile("cp.async.wait_group 1;" ::: "memory");
        } else {
            asm volatile("cp.async.wait_group 0;" ::: "memory");
        }
        __syncthreads();

        const uint32_t stage = sb + (j & 1) * STAGE_BYTES;

        #pragma unroll
        for (int ks = 0; ks < 4; ks++) {
            const int kbyte = ks * 32;
            uint32_t ah[4][4], al[4][4];
            #pragma unroll
            for (int mf = 0; mf < 4; mf++) {
                const uint32_t off = SW128((aRow + mf * 16) * 128 + kbyte + aKb);
                LDMX4(ah[mf][0], ah[mf][1], ah[mf][2], ah[mf][3],
                      stage + S_A_HI + off);
                if constexpr (NPROD == 2) {
                    LDMX4(al[mf][0], al[mf][1], al[mf][2], al[mf][3],
                          stage + S_A_LO + off);
                }
            }
            #pragma unroll
            for (int np = 0; np < 4; np++) {
                const uint32_t off = SW128((bRowBase + np * 16) * 128 + kbyte + bKb);
                uint32_t b0, b1, b2, b3r;
                LDMX4(b0, b1, b2, b3r, stage + S_B + off);
                #pragma unroll
                for (int mf = 0; mf < 4; mf++) {
                    MMAF16(acc[mf][2 * np],     ah[mf][0], ah[mf][1], ah[mf][2], ah[mf][3], b0, b1);
                    MMAF16(acc[mf][2 * np + 1], ah[mf][0], ah[mf][1], ah[mf][2], ah[mf][3], b2, b3r);
                    if constexpr (NPROD == 2) {
                        MMAF16(acc[mf][2 * np],     al[mf][0], al[mf][1], al[mf][2], al[mf][3], b0, b1);
                        MMAF16(acc[mf][2 * np + 1], al[mf][0], al[mf][1], al[mf][2], al[mf][3], b2, b3r);
                    }
                }
            }
        }
    }

    // ---- epilogue ----
    if constexpr (MODE == 1) {
        // bias + relu -> single fp16 h1
        #pragma unroll
        for (int mf = 0; mf < 4; mf++) {
            const int r0 = rowA0 + warpM * 64 + mf * 16 + g;
            const int r1 = r0 + 8;
            #pragma unroll
            for (int nf = 0; nf < 8; nf++) {
                const int col = colB0 + warpN * 64 + nf * 8 + tig * 2;
                const float bx = __ldg(bias + col);
                const float by = __ldg(bias + col + 1);
                __half2 h0, h1;
                h0.x = __float2half_rn(fmaxf(acc[mf][nf][0] + bx, 0.0f));
                h0.y = __float2half_rn(fmaxf(acc[mf][nf][1] + by, 0.0f));
                h1.x = __float2half_rn(fmaxf(acc[mf][nf][2] + bx, 0.0f));
                h1.y = __float2half_rn(fmaxf(acc[mf][nf][3] + by, 0.0f));
                *(__half2*)(outH + (size_t)r0 * Npitch + col) = h0;
                *(__half2*)(outH + (size_t)r1 * Npitch + col) = h1;
            }
        }
    } else {
        // fused GEMV: scores[row] += sum_col relu(h2[row,col]) * w3[col]
        #pragma unroll
        for (int mf = 0; mf < 4; mf++) {
            const int r0 = rowA0 + warpM * 64 + mf * 16 + g;
            const int r1 = r0 + 8;
            float p0 = 0.0f, p1 = 0.0f;
            #pragma unroll
            for (int nf = 0; nf < 8; nf++) {
                const int col = colB0 + warpN * 64 + nf * 8 + tig * 2;
                const float bx = __ldg(bias + col);
                const float by = __ldg(bias + col + 1);
                const float wx = __ldg(w3 + col);
                const float wy = __ldg(w3 + col + 1);
                p0 += fmaxf(acc[mf][nf][0] + bx, 0.0f) * wx
                    + fmaxf(acc[mf][nf][1] + by, 0.0f) * wy;
                p1 += fmaxf(acc[mf][nf][2] + bx, 0.0f) * wx
                    + fmaxf(acc[mf][nf][3] + by, 0.0f) * wy;
            }
            p0 += __shfl_xor_sync(0xffffffffu, p0, 1);
            p0 += __shfl_xor_sync(0xffffffffu, p0, 2);
            p1 += __shfl_xor_sync(0xffffffffu, p1, 1);
            p1 += __shfl_xor_sync(0xffffffffu, p1, 2);
            if (tig == 0) {
                atomicAdd(scores + r0, p0);
                atomicAdd(scores + r1, p1);
            }
        }
    }
}

// ---------------------------------------------------------------------------
// soft_rank (parallel PAV), b3 folded in (rank shift-invariance)
// ---------------------------------------------------------------------------
__device__ __forceinline__ int pav_merge(int Lbase, int nl, int Rbase, int nr,
                                         int* __restrict__ pst,
                                         int* __restrict__ pcn,
                                         float* __restrict__ psm)
{
    int len = nl;
    for (int t = 0; t < nr; t++) {
        int   cs = pst[Rbase + t];
        int   cc = pcn[Rbase + t];
        float cm = psm[Rbase + t];
        while (len > 0) {
            float ts = psm[Lbase + len - 1];
            int   tc = pcn[Lbase + len - 1];
            if (ts * (float)cc < cm * (float)tc) {
                cm += ts; cc += tc; cs = pst[Lbase + len - 1];
                len--;
            } else break;
        }
        pst[Lbase + len] = cs;
        pcn[Lbase + len] = cc;
        psm[Lbase + len] = cm;
        len++;
    }
    return len;
}

__global__ void softrank_kernel(const float* __restrict__ scores,
                                const float* __restrict__ b3,
                                float* __restrict__ out,
                                int n)
{
    extern __shared__ float smf[];
    float* s   = smf;
    float* psm = s + n;
    int*   idx = (int*)(psm + n);
    int*   pst = idx + n;
    int*   pcn = pst + n;
    int*   cA  = pcn + n;
    int*   cB  = cA + n / 2;

    const int tid = threadIdx.x;
    const int nt  = blockDim.x;
    const float b3v = b3[0];

    for (int i = tid; i < n; i += nt) { s[i] = scores[i] + b3v; idx[i] = i; }
    __syncthreads();

    for (int k = 2; k <= n; k <<= 1) {
        for (int j = k >> 1; j > 0; j >>= 1) {
            for (int i = tid; i < n; i += nt) {
                int ixj = i ^ j;
                if (ixj > i) {
                    bool up = ((i & k) == 0);
                    float a = s[i], b = s[ixj];
                    bool sw = up ? (a < b) : (a > b);
                    if (sw) {
                        s[i] = b; s[ixj] = a;
                        int t = idx[i]; idx[i] = idx[ixj]; idx[ixj] = t;
                    }
                }
            }
            __syncthreads();
        }
    }

    for (int i = tid; i < n; i += nt) {
        pst[i] = i;
        pcn[i] = 1;
        psm[i] = s[i] - (float)(n - i);
    }
    __syncthreads();

    for (int g2 = tid; g2 < n / 2; g2 += nt)
        cA[g2] = pav_merge(2 * g2, 1, 2 * g2 + 1, 1, pst, pcn, psm);
    __syncthreads();

    int* cCur = cA;
    int* cNxt = cB;
    for (int L = 2; (1 << L) <= n; L++) {
        const int half = 1 << (L - 1);
        const int nm = n >> L;
        for (int g2 = tid; g2 < nm; g2 += nt)
            cNxt[g2] = pav_merge((g2 << L), cCur[2 * g2],
                                 (g2 << L) + half, cCur[2 * g2 + 1],
                                 pst, pcn, psm);
        __syncthreads();
        int* t = cCur; cCur = cNxt; cNxt = t;
    }
    const int P = cCur[0];

    for (int i = tid; i < n; i += nt) {
        int lo = 0, hi = P - 1;
        while (lo < hi) {
            int mid = (lo + hi + 1) >> 1;
            if (pst[mid] <= i) lo = mid; else hi = mid - 1;
        }
        float dual = psm[lo] / (float)pcn[lo];
        out[idx[i]] = s[i] - dual;      // rank, original order
        out[n + i]  = scores[i] + b3v;  // scores (with bias)
    }
}

// ---------------------------------------------------------------------------
// Launch
// ---------------------------------------------------------------------------
extern "C" void kernel_launch(void* const* d_in, const int* in_sizes, int n_in,
                              void* d_out, int out_size)
{
    const float* x  = (const float*)d_in[0];
    const float* W1 = (const float*)d_in[1];
    const float* b1 = (const float*)d_in[2];
    const float* W2 = (const float*)d_in[3];
    const float* b2 = (const float*)d_in[4];
    const float* W3 = (const float*)d_in[5];
    const float* b3 = (const float*)d_in[6];
    float* out = (float*)d_out;

    __half *xhi, *xlo, *w1, *w2, *h1;
    float *sc;
    cudaGetSymbolAddress((void**)&xhi, g_xhi);
    cudaGetSymbolAddress((void**)&xlo, g_xlo);
    cudaGetSymbolAddress((void**)&w1,  g_w1);
    cudaGetSymbolAddress((void**)&w2,  g_w2);
    cudaGetSymbolAddress((void**)&h1,  g_h1);
    cudaGetSymbolAddress((void**)&sc,  g_scores);

    // conversions
    {
        int n = MB * DIN;
        split_rows_h<<<(n / 4 + 255) / 256, 256>>>(x, xhi, xlo, n);
        transpose_h64<<<dim3(HID / 32, DIN / 64), dim3(32, 8)>>>(W1, w1, DIN, HID);
        transpose_h64<<<dim3(HID / 32, HID / 64), dim3(32, 8)>>>(W2, w2, HID, HID);
    }

    cudaFuncSetAttribute(gemm_mma<2, 1>,
                         cudaFuncAttributeMaxDynamicSharedMemorySize, GEMM_SMEM);
    cudaFuncSetAttribute(gemm_mma<1, 0>,
                         cudaFuncAttributeMaxDynamicSharedMemorySize, GEMM_SMEM);

    // layer 1 (2-product): relu(x @ W1 + b1) -> h1 (single fp16)
    {
        dim3 grid(HID / BN, MB / BM);
        gemm_mma<2, 1><<<grid, 256, GEMM_SMEM>>>(xhi, xlo, w1, b1,
                                                 DIN, HID,
                                                 h1, nullptr, nullptr);
    }
    // layer 2 (1-product) + fused GEMV: scores = relu(h1 @ W2 + b2) @ W3
    zero_scores<<<MB / 1024, 1024>>>(sc);
    {
        dim3 grid(HID / BN, MB / BM);
        gemm_mma<1, 0><<<grid, 256, GEMM_SMEM>>>(h1, nullptr, w2, b2,
                                                 HID, HID,
                                                 nullptr, W3, sc);
    }
    // soft_rank (+ b3)
    {
        size_t smem = (size_t)MB * 6 * sizeof(float);
        cudaFuncSetAttribute(softrank_kernel,
                             cudaFuncAttributeMaxDynamicSharedMemorySize,
                             (int)smem);
        softrank_kernel<<<1, 1024, smem>>>(sc, b3, out, MB);
    }
}

// round 13
// speedup vs baseline: 6.0119x; 1.1243x over previous
#include <cuda_runtime.h>
#include <cuda_fp16.h>
#include <cstdint>

// ---------------------------------------------------------------------------
// Shapes (fixed by the dataset)
// ---------------------------------------------------------------------------
#define MB   4096
#define DIN  512
#define HID  2048

// ---------------------------------------------------------------------------
// Device scratch
// ---------------------------------------------------------------------------
__device__ __half g_x[(size_t)MB * DIN];
__device__ __half g_w1[(size_t)HID * DIN];
__device__ __half g_w2[(size_t)HID * HID];
__device__ __half g_h1[(size_t)MB * HID];
__device__ float g_scores[MB];

// ---------------------------------------------------------------------------
// Helpers
// ---------------------------------------------------------------------------
__device__ __forceinline__ uint32_t smem_u32(const void* p) {
    uint32_t a;
    asm("{ .reg .u64 t; cvta.to.shared.u64 t, %1; cvt.u32.u64 %0, t; }"
        : "=r"(a) : "l"(p));
    return a;
}

#define SW128(o) ((o) ^ (((o) >> 3) & 0x70))

#define CPA16(smem, gptr) \
    asm volatile("cp.async.cg.shared.global [%0], [%1], 16;" \
                 :: "r"(smem), "l"(gptr))

#define LDMX4(r0, r1, r2, r3, addr) \
    asm volatile("ldmatrix.sync.aligned.m8n8.x4.shared.b16 {%0,%1,%2,%3}, [%4];" \
                 : "=r"(r0), "=r"(r1), "=r"(r2), "=r"(r3) : "r"(addr))

#define MMAF16(c, a0, a1, a2, a3, b0, b1) \
    asm volatile("mma.sync.aligned.m16n8k16.row.col.f32.f16.f16.f32 " \
                 "{%0,%1,%2,%3}, {%4,%5,%6,%7}, {%8,%9}, {%0,%1,%2,%3};" \
                 : "+f"((c)[0]), "+f"((c)[1]), "+f"((c)[2]), "+f"((c)[3]) \
                 : "r"(a0), "r"(a1), "r"(a2), "r"(a3), "r"(b0), "r"(b1))

// ---------------------------------------------------------------------------
// Conversions
// ---------------------------------------------------------------------------
__global__ void convert_h(const float* __restrict__ in,
                          __half* __restrict__ out, int n)
{
    int i = (blockIdx.x * blockDim.x + threadIdx.x) * 4;
    if (i >= n) return;
    float4 v = *(const float4*)(in + i);
    __half2 a, b;
    a.x = __float2half_rn(v.x);
    a.y = __float2half_rn(v.y);
    b.x = __float2half_rn(v.z);
    b.y = __float2half_rn(v.w);
    *(__half2*)(out + i)     = a;
    *(__half2*)(out + i + 2) = b;
}

// W [K,N] row-major -> T [N,K] single fp16, 64-wide k tiles
__global__ void transpose_h64(const float* __restrict__ W,
                              __half* __restrict__ T, int K, int N)
{
    __shared__ float t[64][33];
    const int n0 = blockIdx.x * 32, k0 = blockIdx.y * 64;
    const int tx = threadIdx.x, ty = threadIdx.y;
    #pragma unroll
    for (int r = ty; r < 64; r += 8)
        t[r][tx] = W[(size_t)(k0 + r) * N + n0 + tx];
    __syncthreads();
    #pragma unroll
    for (int nr = ty; nr < 32; nr += 8) {
        __half2 h;
        h.x = __float2half_rn(t[tx * 2][nr]);
        h.y = __float2half_rn(t[tx * 2 + 1][nr]);
        *(__half2*)(T + (size_t)(n0 + nr) * K + k0 + tx * 2) = h;
    }
}

__global__ void zero_scores(float* __restrict__ s)
{
    s[blockIdx.x * 1024 + threadIdx.x] = 0.0f;
}

// ---------------------------------------------------------------------------
// fp16 single-product GEMM: D = relu(A @ B^T + bias).
// A [M,K] fp16 K-major; B [N,K] fp16 K-major.
// CTA 128x256, 256 threads, warp grid 2x4, warp tile 64x64, KC=64, 2-stage.
// MODE=1: write single fp16 h1.  MODE=0: fused GEMV into scores.
// ---------------------------------------------------------------------------
#define BM 128
#define BN 256
#define KC 64
#define S_A 0
#define S_B 16384
#define STAGE_BYTES 49152          // A 16K + B 32K
#define GEMM_SMEM (2 * STAGE_BYTES)   // 98304

template<int MODE>
__global__ __launch_bounds__(256, 1)
void gemm_mma(const __half* __restrict__ A,
              const __half* __restrict__ B,
              const float* __restrict__ bias,
              int K, int Npitch,
              __half* __restrict__ outH,
              const float* __restrict__ w3,
              float* __restrict__ scores)
{
    extern __shared__ char smem[];
    const uint32_t sb = smem_u32(smem);

    const int tid   = threadIdx.x;
    const int lane  = tid & 31;
    const int w     = tid >> 5;
    const int warpM = w >> 2;          // 0..1 (64 rows)
    const int warpN = w & 3;           // 0..3 (64 cols)
    const int g     = lane >> 2;
    const int tig   = lane & 3;

    const int rowA0 = blockIdx.y * BM;
    const int colB0 = blockIdx.x * BN;
    const int nch   = K / KC;

    float acc[4][8][4];
    #pragma unroll
    for (int mf = 0; mf < 4; mf++)
        #pragma unroll
        for (int nf = 0; nf < 8; nf++)
            #pragma unroll
            for (int e = 0; e < 4; e++)
                acc[mf][nf][e] = 0.0f;

    auto load_chunk = [&](int j, int st) {
        const uint32_t stage = sb + st * STAGE_BYTES;
        const size_t cOff = (size_t)j * KC;
        // A tile: 128 rows x 8 segs = 1024 segs
        #pragma unroll
        for (int u = 0; u < 4; u++) {
            const int seg = u * 256 + tid;
            const int r = seg >> 3;
            const int s = (seg & 7) << 4;
            const uint32_t sw = SW128(r * 128 + s);
            const char* gp = (const char*)(A + (size_t)(rowA0 + r) * K + cOff) + s;
            CPA16(stage + S_A + sw, gp);
        }
        // B tile: 256 rows x 8 segs = 2048 segs
        #pragma unroll
        for (int u = 0; u < 8; u++) {
            const int seg = u * 256 + tid;
            const int r = seg >> 3;
            const int s = (seg & 7) << 4;
            const uint32_t sw = SW128(r * 128 + s);
            const char* gp = (const char*)(B + (size_t)(colB0 + r) * K + cOff) + s;
            CPA16(stage + S_B + sw, gp);
        }
        asm volatile("cp.async.commit_group;");
    };

    const int aRow = warpM * 64 + (lane & 7) + ((lane >> 3) & 1) * 8;
    const int aKb  = ((lane >> 4) & 1) * 16;
    const int bRowBase = warpN * 64 + ((lane >> 4) & 1) * 8 + (lane & 7);
    const int bKb  = ((lane >> 3) & 1) * 16;

    load_chunk(0, 0);

    for (int j = 0; j < nch; j++) {
        __syncthreads();
        if (j + 1 < nch) {
            load_chunk(j + 1, (j + 1) & 1);
            asm volatile("cp.async.wait_group 1;" ::: "memory");
        } else {
            asm volatile("cp.async.wait_group 0;" ::: "memory");
        }
        __syncthreads();

        const uint32_t stage = sb + (j & 1) * STAGE_BYTES;

        #pragma unroll
        for (int ks = 0; ks < 4; ks++) {
            const int kbyte = ks * 32;
            uint32_t a[4][4];
            #pragma unroll
            for (int mf = 0; mf < 4; mf++) {
                const uint32_t off = SW128((aRow + mf * 16) * 128 + kbyte + aKb);
                LDMX4(a[mf][0], a[mf][1], a[mf][2], a[mf][3],
                      stage + S_A + off);
            }
            #pragma unroll
            for (int np = 0; np < 4; np++) {
                const uint32_t off = SW128((bRowBase + np * 16) * 128 + kbyte + bKb);
                uint32_t b0, b1, b2, b3r;
                LDMX4(b0, b1, b2, b3r, stage + S_B + off);
                #pragma unroll
                for (int mf = 0; mf < 4; mf++) {
                    MMAF16(acc[mf][2 * np],     a[mf][0], a[mf][1], a[mf][2], a[mf][3], b0, b1);
                    MMAF16(acc[mf][2 * np + 1], a[mf][0], a[mf][1], a[mf][2], a[mf][3], b2, b3r);
                }
            }
        }
    }

    // ---- epilogue ----
    if constexpr (MODE == 1) {
        #pragma unroll
        for (int mf = 0; mf < 4; mf++) {
            const int r0 = rowA0 + warpM * 64 + mf * 16 + g;
            const int r1 = r0 + 8;
            #pragma unroll
            for (int nf = 0; nf < 8; nf++) {
                const int col = colB0 + warpN * 64 + nf * 8 + tig * 2;
                const float bx = __ldg(bias + col);
                const float by = __ldg(bias + col + 1);
                __half2 h0, h1;
                h0.x = __float2half_rn(fmaxf(acc[mf][nf][0] + bx, 0.0f));
                h0.y = __float2half_rn(fmaxf(acc[mf][nf][1] + by, 0.0f));
                h1.x = __float2half_rn(fmaxf(acc[mf][nf][2] + bx, 0.0f));
                h1.y = __float2half_rn(fmaxf(acc[mf][nf][3] + by, 0.0f));
                *(__half2*)(outH + (size_t)r0 * Npitch + col) = h0;
                *(__half2*)(outH + (size_t)r1 * Npitch + col) = h1;
            }
        }
    } else {
        // fused GEMV: scores[row] += sum_col relu(h2[row,col]) * w3[col]
        #pragma unroll
        for (int mf = 0; mf < 4; mf++) {
            const int r0 = rowA0 + warpM * 64 + mf * 16 + g;
            const int r1 = r0 + 8;
            float p0 = 0.0f, p1 = 0.0f;
            #pragma unroll
            for (int nf = 0; nf < 8; nf++) {
                const int col = colB0 + warpN * 64 + nf * 8 + tig * 2;
                const float bx = __ldg(bias + col);
                const float by = __ldg(bias + col + 1);
                const float wx = __ldg(w3 + col);
                const float wy = __ldg(w3 + col + 1);
                p0 += fmaxf(acc[mf][nf][0] + bx, 0.0f) * wx
                    + fmaxf(acc[mf][nf][1] + by, 0.0f) * wy;
                p1 += fmaxf(acc[mf][nf][2] + bx, 0.0f) * wx
                    + fmaxf(acc[mf][nf][3] + by, 0.0f) * wy;
            }
            p0 += __shfl_xor_sync(0xffffffffu, p0, 1);
            p0 += __shfl_xor_sync(0xffffffffu, p0, 2);
            p1 += __shfl_xor_sync(0xffffffffu, p1, 1);
            p1 += __shfl_xor_sync(0xffffffffu, p1, 2);
            if (tig == 0) {
                atomicAdd(scores + r0, p0);
                atomicAdd(scores + r1, p1);
            }
        }
    }
}

// ---------------------------------------------------------------------------
// soft_rank (parallel PAV), b3 folded in (rank shift-invariance)
// ---------------------------------------------------------------------------
__device__ __forceinline__ int pav_merge(int Lbase, int nl, int Rbase, int nr,
                                         int* __restrict__ pst,
                                         int* __restrict__ pcn,
                                         float* __restrict__ psm)
{
    int len = nl;
    for (int t = 0; t < nr; t++) {
        int   cs = pst[Rbase + t];
        int   cc = pcn[Rbase + t];
        float cm = psm[Rbase + t];
        while (len > 0) {
            float ts = psm[Lbase + len - 1];
            int   tc = pcn[Lbase + len - 1];
            if (ts * (float)cc < cm * (float)tc) {
                cm += ts; cc += tc; cs = pst[Lbase + len - 1];
                len--;
            } else break;
        }
        pst[Lbase + len] = cs;
        pcn[Lbase + len] = cc;
        psm[Lbase + len] = cm;
        len++;
    }
    return len;
}

__global__ void softrank_kernel(const float* __restrict__ scores,
                                const float* __restrict__ b3,
                                float* __restrict__ out,
                                int n)
{
    extern __shared__ float smf[];
    float* s   = smf;
    float* psm = s + n;
    int*   idx = (int*)(psm + n);
    int*   pst = idx + n;
    int*   pcn = pst + n;
    int*   cA  = pcn + n;
    int*   cB  = cA + n / 2;

    const int tid = threadIdx.x;
    const int nt  = blockDim.x;
    const float b3v = b3[0];

    for (int i = tid; i < n; i += nt) { s[i] = scores[i] + b3v; idx[i] = i; }
    __syncthreads();

    for (int k = 2; k <= n; k <<= 1) {
        for (int j = k >> 1; j > 0; j >>= 1) {
            for (int i = tid; i < n; i += nt) {
                int ixj = i ^ j;
                if (ixj > i) {
                    bool up = ((i & k) == 0);
                    float a = s[i], b = s[ixj];
                    bool sw = up ? (a < b) : (a > b);
                    if (sw) {
                        s[i] = b; s[ixj] = a;
                        int t = idx[i]; idx[i] = idx[ixj]; idx[ixj] = t;
                    }
                }
            }
            __syncthreads();
        }
    }

    for (int i = tid; i < n; i += nt) {
        pst[i] = i;
        pcn[i] = 1;
        psm[i] = s[i] - (float)(n - i);
    }
    __syncthreads();

    for (int g2 = tid; g2 < n / 2; g2 += nt)
        cA[g2] = pav_merge(2 * g2, 1, 2 * g2 + 1, 1, pst, pcn, psm);
    __syncthreads();

    int* cCur = cA;
    int* cNxt = cB;
    for (int L = 2; (1 << L) <= n; L++) {
        const int half = 1 << (L - 1);
        const int nm = n >> L;
        for (int g2 = tid; g2 < nm; g2 += nt)
            cNxt[g2] = pav_merge((g2 << L), cCur[2 * g2],
                                 (g2 << L) + half, cCur[2 * g2 + 1],
                                 pst, pcn, psm);
        __syncthreads();
        int* t = cCur; cCur = cNxt; cNxt = t;
    }
    const int P = cCur[0];

    for (int i = tid; i < n; i += nt) {
        int lo = 0, hi = P - 1;
        while (lo < hi) {
            int mid = (lo + hi + 1) >> 1;
            if (pst[mid] <= i) lo = mid; else hi = mid - 1;
        }
        float dual = psm[lo] / (float)pcn[lo];
        out[idx[i]] = s[i] - dual;      // rank, original order
        out[n + i]  = scores[i] + b3v;  // scores (with bias)
    }
}

// ---------------------------------------------------------------------------
// Launch
// ---------------------------------------------------------------------------
extern "C" void kernel_launch(void* const* d_in, const int* in_sizes, int n_in,
                              void* d_out, int out_size)
{
    const float* x  = (const float*)d_in[0];
    const float* W1 = (const float*)d_in[1];
    const float* b1 = (const float*)d_in[2];
    const float* W2 = (const float*)d_in[3];
    const float* b2 = (const float*)d_in[4];
    const float* W3 = (const float*)d_in[5];
    const float* b3 = (const float*)d_in[6];
    float* out = (float*)d_out;

    __half *xh, *w1, *w2, *h1;
    float *sc;
    cudaGetSymbolAddress((void**)&xh, g_x);
    cudaGetSymbolAddress((void**)&w1, g_w1);
    cudaGetSymbolAddress((void**)&w2, g_w2);
    cudaGetSymbolAddress((void**)&h1, g_h1);
    cudaGetSymbolAddress((void**)&sc, g_scores);

    // conversions
    {
        int n = MB * DIN;
        convert_h<<<(n / 4 + 255) / 256, 256>>>(x, xh, n);
        transpose_h64<<<dim3(HID / 32, DIN / 64), dim3(32, 8)>>>(W1, w1, DIN, HID);
        transpose_h64<<<dim3(HID / 32, HID / 64), dim3(32, 8)>>>(W2, w2, HID, HID);
    }

    cudaFuncSetAttribute(gemm_mma<1>,
                         cudaFuncAttributeMaxDynamicSharedMemorySize, GEMM_SMEM);
    cudaFuncSetAttribute(gemm_mma<0>,
                         cudaFuncAttributeMaxDynamicSharedMemorySize, GEMM_SMEM);

    // layer 1: relu(x @ W1 + b1) -> h1 (fp16)
    {
        dim3 grid(HID / BN, MB / BM);
        gemm_mma<1><<<grid, 256, GEMM_SMEM>>>(xh, w1, b1, DIN, HID,
                                              h1, nullptr, nullptr);
    }
    // layer 2 + fused GEMV: scores = relu(h1 @ W2 + b2) @ W3
    zero_scores<<<MB / 1024, 1024>>>(sc);
    {
        dim3 grid(HID / BN, MB / BM);
        gemm_mma<0><<<grid, 256, GEMM_SMEM>>>(h1, w2, b2, HID, HID,
                                              nullptr, W3, sc);
    }
    // soft_rank (+ b3)
    {
        size_t smem = (size_t)MB * 6 * sizeof(float);
        cudaFuncSetAttribute(softrank_kernel,
                             cudaFuncAttributeMaxDynamicSharedMemorySize,
                             (int)smem);
        softrank_kernel<<<1, 1024, smem>>>(sc, b3, out, MB);
    }
}

// round 14
// speedup vs baseline: 6.1295x; 1.0196x over previous
#include <cuda_runtime.h>
#include <cuda_fp16.h>
#include <cstdint>

// ---------------------------------------------------------------------------
// Shapes (fixed by the dataset)
// ---------------------------------------------------------------------------
#define MB   4096
#define DIN  512
#define HID  2048

// ---------------------------------------------------------------------------
// Device scratch
// ---------------------------------------------------------------------------
__device__ __half g_x[(size_t)MB * DIN];
__device__ __half g_w1[(size_t)HID * DIN];
__device__ __half g_w2[(size_t)HID * HID];
__device__ __half g_h1[(size_t)MB * HID];
__device__ float g_scores[MB];

// ---------------------------------------------------------------------------
// Helpers
// ---------------------------------------------------------------------------
__device__ __forceinline__ uint32_t smem_u32(const void* p) {
    uint32_t a;
    asm("{ .reg .u64 t; cvta.to.shared.u64 t, %1; cvt.u32.u64 %0, t; }"
        : "=r"(a) : "l"(p));
    return a;
}

#define SW128(o) ((o) ^ (((o) >> 3) & 0x70))

#define CPA16(smem, gptr) \
    asm volatile("cp.async.cg.shared.global [%0], [%1], 16;" \
                 :: "r"(smem), "l"(gptr))

#define LDMX4(r0, r1, r2, r3, addr) \
    asm volatile("ldmatrix.sync.aligned.m8n8.x4.shared.b16 {%0,%1,%2,%3}, [%4];" \
                 : "=r"(r0), "=r"(r1), "=r"(r2), "=r"(r3) : "r"(addr))

#define MMAF16(c, a0, a1, a2, a3, b0, b1) \
    asm volatile("mma.sync.aligned.m16n8k16.row.col.f32.f16.f16.f32 " \
                 "{%0,%1,%2,%3}, {%4,%5,%6,%7}, {%8,%9}, {%0,%1,%2,%3};" \
                 : "+f"((c)[0]), "+f"((c)[1]), "+f"((c)[2]), "+f"((c)[3]) \
                 : "r"(a0), "r"(a1), "r"(a2), "r"(a3), "r"(b0), "r"(b1))

// ---------------------------------------------------------------------------
// Conversions
// ---------------------------------------------------------------------------
__global__ void convert_h(const float* __restrict__ in,
                          __half* __restrict__ out, int n)
{
    int i = (blockIdx.x * blockDim.x + threadIdx.x) * 4;
    if (i >= n) return;
    float4 v = *(const float4*)(in + i);
    __half2 a, b;
    a.x = __float2half_rn(v.x);
    a.y = __float2half_rn(v.y);
    b.x = __float2half_rn(v.z);
    b.y = __float2half_rn(v.w);
    *(__half2*)(out + i)     = a;
    *(__half2*)(out + i + 2) = b;
}

// W [K,N] row-major fp32 -> T [N,K] fp16. 64x64 tiles, float4 loads,
// half2 stores. grid (N/64, K/64), 256 threads.
__global__ __launch_bounds__(256)
void transpose_h64v(const float* __restrict__ W,
                    __half* __restrict__ T, int K, int N)
{
    __shared__ float t[64][65];
    const int n0 = blockIdx.x * 64, k0 = blockIdx.y * 64;
    const int tid = threadIdx.x;
    #pragma unroll
    for (int u = 0; u < 4; u++) {
        const int idx = u * 256 + tid;      // 0..1023
        const int r  = idx >> 4;            // k-row 0..63
        const int c4 = idx & 15;            // float4 column
        float4 v = *(const float4*)(W + (size_t)(k0 + r) * N + n0 + c4 * 4);
        t[r][c4 * 4 + 0] = v.x;
        t[r][c4 * 4 + 1] = v.y;
        t[r][c4 * 4 + 2] = v.z;
        t[r][c4 * 4 + 3] = v.w;
    }
    __syncthreads();
    #pragma unroll
    for (int u = 0; u < 8; u++) {
        const int idx = u * 256 + tid;      // 0..2047
        const int nr = idx >> 5;            // n-row 0..63
        const int kc = idx & 31;            // half2 column
        __half2 h;
        h.x = __float2half_rn(t[kc * 2][nr]);
        h.y = __float2half_rn(t[kc * 2 + 1][nr]);
        *(__half2*)(T + (size_t)(n0 + nr) * K + k0 + kc * 2) = h;
    }
}

__global__ void zero_scores(float* __restrict__ s)
{
    s[blockIdx.x * 1024 + threadIdx.x] = 0.0f;
}

// ---------------------------------------------------------------------------
// fp16 single-product GEMM: D = relu(A @ B^T + bias).
// A [M,K] fp16 K-major; B [N,K] fp16 K-major.
// CTA 128x256, 256 threads, warp grid 2x4, warp tile 64x64.
// KC=128 per stage as TWO 64-wide SW128 sub-tiles; one barrier pair and one
// cp.async group per 128-K (half the barriers of KC=64).
// MODE=1: write single fp16 h1.  MODE=0: fused GEMV into scores.
// ---------------------------------------------------------------------------
#define BM 128
#define BN 256
#define KC 128
// per-stage layout: A half0 16K | A half1 16K | B half0 32K | B half1 32K
#define S_A0 0
#define S_A1 16384
#define S_B0 32768
#define S_B1 65536
#define STAGE_BYTES 98304
#define GEMM_SMEM (2 * STAGE_BYTES)   // 196608

template<int MODE>
__global__ __launch_bounds__(256, 1)
void gemm_mma(const __half* __restrict__ A,
              const __half* __restrict__ B,
              const float* __restrict__ bias,
              int K, int Npitch,
              __half* __restrict__ outH,
              const float* __restrict__ w3,
              float* __restrict__ scores)
{
    extern __shared__ char smem[];
    const uint32_t sb = smem_u32(smem);

    const int tid   = threadIdx.x;
    const int lane  = tid & 31;
    const int w     = tid >> 5;
    const int warpM = w >> 2;          // 0..1 (64 rows)
    const int warpN = w & 3;           // 0..3 (64 cols)
    const int g     = lane >> 2;
    const int tig   = lane & 3;

    const int rowA0 = blockIdx.y * BM;
    const int colB0 = blockIdx.x * BN;
    const int nch   = K / KC;

    float acc[4][8][4];
    #pragma unroll
    for (int mf = 0; mf < 4; mf++)
        #pragma unroll
        for (int nf = 0; nf < 8; nf++)
            #pragma unroll
            for (int e = 0; e < 4; e++)
                acc[mf][nf][e] = 0.0f;

    auto load_chunk = [&](int j, int st) {
        const uint32_t stage = sb + st * STAGE_BYTES;
        #pragma unroll
        for (int h = 0; h < 2; h++) {
            const size_t cOff = (size_t)j * KC + h * 64;
            const uint32_t aBase = stage + (h ? S_A1 : S_A0);
            const uint32_t bBase = stage + (h ? S_B1 : S_B0);
            // A sub-tile: 128 rows x 8 segs = 1024 segs
            #pragma unroll
            for (int u = 0; u < 4; u++) {
                const int seg = u * 256 + tid;
                const int r = seg >> 3;
                const int s = (seg & 7) << 4;
                const uint32_t sw = SW128(r * 128 + s);
                const char* gp = (const char*)(A + (size_t)(rowA0 + r) * K + cOff) + s;
                CPA16(aBase + sw, gp);
            }
            // B sub-tile: 256 rows x 8 segs = 2048 segs
            #pragma unroll
            for (int u = 0; u < 8; u++) {
                const int seg = u * 256 + tid;
                const int r = seg >> 3;
                const int s = (seg & 7) << 4;
                const uint32_t sw = SW128(r * 128 + s);
                const char* gp = (const char*)(B + (size_t)(colB0 + r) * K + cOff) + s;
                CPA16(bBase + sw, gp);
            }
        }
        asm volatile("cp.async.commit_group;");
    };

    const int aRow = warpM * 64 + (lane & 7) + ((lane >> 3) & 1) * 8;
    const int aKb  = ((lane >> 4) & 1) * 16;
    const int bRowBase = warpN * 64 + ((lane >> 4) & 1) * 8 + (lane & 7);
    const int bKb  = ((lane >> 3) & 1) * 16;

    load_chunk(0, 0);

    for (int j = 0; j < nch; j++) {
        __syncthreads();
        if (j + 1 < nch) {
            load_chunk(j + 1, (j + 1) & 1);
            asm volatile("cp.async.wait_group 1;" ::: "memory");
        } else {
            asm volatile("cp.async.wait_group 0;" ::: "memory");
        }
        __syncthreads();

        const uint32_t stage = sb + (j & 1) * STAGE_BYTES;

        #pragma unroll
        for (int h = 0; h < 2; h++) {
            const uint32_t aBase = stage + (h ? S_A1 : S_A0);
            const uint32_t bBase = stage + (h ? S_B1 : S_B0);
            #pragma unroll
            for (int ks = 0; ks < 4; ks++) {
                const int kbyte = ks * 32;
                uint32_t a[4][4];
                #pragma unroll
                for (int mf = 0; mf < 4; mf++) {
                    const uint32_t off = SW128((aRow + mf * 16) * 128 + kbyte + aKb);
                    LDMX4(a[mf][0], a[mf][1], a[mf][2], a[mf][3], aBase + off);
                }
                #pragma unroll
                for (int np = 0; np < 4; np++) {
                    const uint32_t off = SW128((bRowBase + np * 16) * 128 + kbyte + bKb);
                    uint32_t b0, b1, b2, b3r;
                    LDMX4(b0, b1, b2, b3r, bBase + off);
                    #pragma unroll
                    for (int mf = 0; mf < 4; mf++) {
                        MMAF16(acc[mf][2 * np],     a[mf][0], a[mf][1], a[mf][2], a[mf][3], b0, b1);
                        MMAF16(acc[mf][2 * np + 1], a[mf][0], a[mf][1], a[mf][2], a[mf][3], b2, b3r);
                    }
                }
            }
        }
    }

    // ---- epilogue ----
    if constexpr (MODE == 1) {
        #pragma unroll
        for (int mf = 0; mf < 4; mf++) {
            const int r0 = rowA0 + warpM * 64 + mf * 16 + g;
            const int r1 = r0 + 8;
            #pragma unroll
            for (int nf = 0; nf < 8; nf++) {
                const int col = colB0 + warpN * 64 + nf * 8 + tig * 2;
                const float bx = __ldg(bias + col);
                const float by = __ldg(bias + col + 1);
                __half2 h0, h1;
                h0.x = __float2half_rn(fmaxf(acc[mf][nf][0] + bx, 0.0f));
                h0.y = __float2half_rn(fmaxf(acc[mf][nf][1] + by, 0.0f));
                h1.x = __float2half_rn(fmaxf(acc[mf][nf][2] + bx, 0.0f));
                h1.y = __float2half_rn(fmaxf(acc[mf][nf][3] + by, 0.0f));
                *(__half2*)(outH + (size_t)r0 * Npitch + col) = h0;
                *(__half2*)(outH + (size_t)r1 * Npitch + col) = h1;
            }
        }
    } else {
        // fused GEMV: scores[row] += sum_col relu(h2[row,col]) * w3[col]
        #pragma unroll
        for (int mf = 0; mf < 4; mf++) {
            const int r0 = rowA0 + warpM * 64 + mf * 16 + g;
            const int r1 = r0 + 8;
            float p0 = 0.0f, p1 = 0.0f;
            #pragma unroll
            for (int nf = 0; nf < 8; nf++) {
                const int col = colB0 + warpN * 64 + nf * 8 + tig * 2;
                const float bx = __ldg(bias + col);
                const float by = __ldg(bias + col + 1);
                const float wx = __ldg(w3 + col);
                const float wy = __ldg(w3 + col + 1);
                p0 += fmaxf(acc[mf][nf][0] + bx, 0.0f) * wx
                    + fmaxf(acc[mf][nf][1] + by, 0.0f) * wy;
                p1 += fmaxf(acc[mf][nf][2] + bx, 0.0f) * wx
                    + fmaxf(acc[mf][nf][3] + by, 0.0f) * wy;
            }
            p0 += __shfl_xor_sync(0xffffffffu, p0, 1);
            p0 += __shfl_xor_sync(0xffffffffu, p0, 2);
            p1 += __shfl_xor_sync(0xffffffffu, p1, 1);
            p1 += __shfl_xor_sync(0xffffffffu, p1, 2);
            if (tig == 0) {
                atomicAdd(scores + r0, p0);
                atomicAdd(scores + r1, p1);
            }
        }
    }
}

// ---------------------------------------------------------------------------
// soft_rank (parallel PAV), b3 folded in (rank shift-invariance)
// ---------------------------------------------------------------------------
__device__ __forceinline__ int pav_merge(int Lbase, int nl, int Rbase, int nr,
                                         int* __restrict__ pst,
                                         int* __restrict__ pcn,
                                         float* __restrict__ psm)
{
    int len = nl;
    for (int t = 0; t < nr; t++) {
        int   cs = pst[Rbase + t];
        int   cc = pcn[Rbase + t];
        float cm = psm[Rbase + t];
        while (len > 0) {
            float ts = psm[Lbase + len - 1];
            int   tc = pcn[Lbase + len - 1];
            if (ts * (float)cc < cm * (float)tc) {
                cm += ts; cc += tc; cs = pst[Lbase + len - 1];
                len--;
            } else break;
        }
        pst[Lbase + len] = cs;
        pcn[Lbase + len] = cc;
        psm[Lbase + len] = cm;
        len++;
    }
    return len;
}

__global__ void softrank_kernel(const float* __restrict__ scores,
                                const float* __restrict__ b3,
                                float* __restrict__ out,
                                int n)
{
    extern __shared__ float smf[];
    float* s   = smf;
    float* psm = s + n;
    int*   idx = (int*)(psm + n);
    int*   pst = idx + n;
    int*   pcn = pst + n;
    int*   cA  = pcn + n;
    int*   cB  = cA + n / 2;

    const int tid = threadIdx.x;
    const int nt  = blockDim.x;
    const float b3v = b3[0];

    for (int i = tid; i < n; i += nt) { s[i] = scores[i] + b3v; idx[i] = i; }
    __syncthreads();

    for (int k = 2; k <= n; k <<= 1) {
        for (int j = k >> 1; j > 0; j >>= 1) {
            for (int i = tid; i < n; i += nt) {
                int ixj = i ^ j;
                if (ixj > i) {
                    bool up = ((i & k) == 0);
                    float a = s[i], b = s[ixj];
                    bool sw = up ? (a < b) : (a > b);
                    if (sw) {
                        s[i] = b; s[ixj] = a;
                        int t = idx[i]; idx[i] = idx[ixj]; idx[ixj] = t;
                    }
                }
            }
            __syncthreads();
        }
    }

    for (int i = tid; i < n; i += nt) {
        pst[i] = i;
        pcn[i] = 1;
        psm[i] = s[i] - (float)(n - i);
    }
    __syncthreads();

    for (int g2 = tid; g2 < n / 2; g2 += nt)
        cA[g2] = pav_merge(2 * g2, 1, 2 * g2 + 1, 1, pst, pcn, psm);
    __syncthreads();

    int* cCur = cA;
    int* cNxt = cB;
    for (int L = 2; (1 << L) <= n; L++) {
        const int half = 1 << (L - 1);
        const int nm = n >> L;
        for (int g2 = tid; g2 < nm; g2 += nt)
            cNxt[g2] = pav_merge((g2 << L), cCur[2 * g2],
                                 (g2 << L) + half, cCur[2 * g2 + 1],
                                 pst, pcn, psm);
        __syncthreads();
        int* t = cCur; cCur = cNxt; cNxt = t;
    }
    const int P = cCur[0];

    for (int i = tid; i < n; i += nt) {
        int lo = 0, hi = P - 1;
        while (lo < hi) {
            int mid = (lo + hi + 1) >> 1;
            if (pst[mid] <= i) lo = mid; else hi = mid - 1;
        }
        float dual = psm[lo] / (float)pcn[lo];
        out[idx[i]] = s[i] - dual;      // rank, original order
        out[n + i]  = scores[i] + b3v;  // scores (with bias)
    }
}

// ---------------------------------------------------------------------------
// Launch
// ---------------------------------------------------------------------------
extern "C" void kernel_launch(void* const* d_in, const int* in_sizes, int n_in,
                              void* d_out, int out_size)
{
    const float* x  = (const float*)d_in[0];
    const float* W1 = (const float*)d_in[1];
    const float* b1 = (const float*)d_in[2];
    const float* W2 = (const float*)d_in[3];
    const float* b2 = (const float*)d_in[4];
    const float* W3 = (const float*)d_in[5];
    const float* b3 = (const float*)d_in[6];
    float* out = (float*)d_out;

    __half *xh, *w1, *w2, *h1;
    float *sc;
    cudaGetSymbolAddress((void**)&xh, g_x);
    cudaGetSymbolAddress((void**)&w1, g_w1);
    cudaGetSymbolAddress((void**)&w2, g_w2);
    cudaGetSymbolAddress((void**)&h1, g_h1);
    cudaGetSymbolAddress((void**)&sc, g_scores);

    // conversions
    {
        int n = MB * DIN;
        convert_h<<<(n / 4 + 255) / 256, 256>>>(x, xh, n);
        transpose_h64v<<<dim3(HID / 64, DIN / 64), 256>>>(W1, w1, DIN, HID);
        transpose_h64v<<<dim3(HID / 64, HID / 64), 256>>>(W2, w2, HID, HID);
    }

    cudaFuncSetAttribute(gemm_mma<1>,
                         cudaFuncAttributeMaxDynamicSharedMemorySize, GEMM_SMEM);
    cudaFuncSetAttribute(gemm_mma<0>,
                         cudaFuncAttributeMaxDynamicSharedMemorySize, GEMM_SMEM);

    // layer 1: relu(x @ W1 + b1) -> h1 (fp16)
    {
        dim3 grid(HID / BN, MB / BM);
        gemm_mma<1><<<grid, 256, GEMM_SMEM>>>(xh, w1, b1, DIN, HID,
                                              h1, nullptr, nullptr);
    }
    // layer 2 + fused GEMV: scores = relu(h1 @ W2 + b2) @ W3
    zero_scores<<<MB / 1024, 1024>>>(sc);
    {
        dim3 grid(HID / BN, MB / BM);
        gemm_mma<0><<<grid, 256, GEMM_SMEM>>>(h1, w2, b2, HID, HID,
                                              nullptr, W3, sc);
    }
    // soft_rank (+ b3)
    {
        size_t smem = (size_t)MB * 6 * sizeof(float);
        cudaFuncSetAttribute(softrank_kernel,
                             cudaFuncAttributeMaxDynamicSharedMemorySize,
                             (int)smem);
        softrank_kernel<<<1, 1024, smem>>>(sc, b3, out, MB);
    }
}

// round 15
// speedup vs baseline: 6.2088x; 1.0129x over previous
#include <cuda_runtime.h>
#include <cuda_fp16.h>
#include <cstdint>

// ---------------------------------------------------------------------------
// Shapes (fixed by the dataset)
// ---------------------------------------------------------------------------
#define MB   4096
#define DIN  512
#define HID  2048

// ---------------------------------------------------------------------------
// Device scratch
// ---------------------------------------------------------------------------
__device__ __half g_x[(size_t)MB * DIN];
__device__ __half g_w1[(size_t)HID * DIN];
__device__ __half g_w2[(size_t)HID * HID];
__device__ __half g_h1[(size_t)MB * HID];
__device__ float g_scores[MB];

// ---------------------------------------------------------------------------
// Helpers
// ---------------------------------------------------------------------------
__device__ __forceinline__ uint32_t smem_u32(const void* p) {
    uint32_t a;
    asm("{ .reg .u64 t; cvta.to.shared.u64 t, %1; cvt.u32.u64 %0, t; }"
        : "=r"(a) : "l"(p));
    return a;
}

#define SW128(o) ((o) ^ (((o) >> 3) & 0x70))

#define CPA16(smem, gptr) \
    asm volatile("cp.async.cg.shared.global [%0], [%1], 16;" \
                 :: "r"(smem), "l"(gptr))

#define LDMX4(r0, r1, r2, r3, addr) \
    asm volatile("ldmatrix.sync.aligned.m8n8.x4.shared.b16 {%0,%1,%2,%3}, [%4];" \
                 : "=r"(r0), "=r"(r1), "=r"(r2), "=r"(r3) : "r"(addr))

#define MMAF16(c, a0, a1, a2, a3, b0, b1) \
    asm volatile("mma.sync.aligned.m16n8k16.row.col.f32.f16.f16.f32 " \
                 "{%0,%1,%2,%3}, {%4,%5,%6,%7}, {%8,%9}, {%0,%1,%2,%3};" \
                 : "+f"((c)[0]), "+f"((c)[1]), "+f"((c)[2]), "+f"((c)[3]) \
                 : "r"(a0), "r"(a1), "r"(a2), "r"(a3), "r"(b0), "r"(b1))

// ---------------------------------------------------------------------------
// Fused prep kernel: one launch does
//   blocks [0, XB):            x fp32 -> fp16
//   blocks [XB, XB+T1B):       W1 [DIN,HID] -> w1t [HID,DIN] fp16
//   blocks [.., +T2B):         W2 [HID,HID] -> w2t [HID,HID] fp16
//   blocks [.., +4):           zero scores
// ---------------------------------------------------------------------------
#define XB  2048                    // (MB*DIN)/(256*4)
#define T1B (HID / 64 * (DIN / 64)) // 256
#define T2B (HID / 64 * (HID / 64)) // 1024
#define PREP_BLOCKS (XB + T1B + T2B + 4)

__device__ __forceinline__ void transpose_tile64(const float* __restrict__ W,
                                                 __half* __restrict__ T,
                                                 int K, int N,
                                                 int bx, int by, int tid,
                                                 float (*t)[65])
{
    const int n0 = bx * 64, k0 = by * 64;
    #pragma unroll
    for (int u = 0; u < 4; u++) {
        const int idx = u * 256 + tid;
        const int r  = idx >> 4;
        const int c4 = idx & 15;
        float4 v = *(const float4*)(W + (size_t)(k0 + r) * N + n0 + c4 * 4);
        t[r][c4 * 4 + 0] = v.x;
        t[r][c4 * 4 + 1] = v.y;
        t[r][c4 * 4 + 2] = v.z;
        t[r][c4 * 4 + 3] = v.w;
    }
    __syncthreads();
    #pragma unroll
    for (int u = 0; u < 8; u++) {
        const int idx = u * 256 + tid;
        const int nr = idx >> 5;
        const int kc = idx & 31;
        __half2 h;
        h.x = __float2half_rn(t[kc * 2][nr]);
        h.y = __float2half_rn(t[kc * 2 + 1][nr]);
        *(__half2*)(T + (size_t)(n0 + nr) * K + k0 + kc * 2) = h;
    }
}

__global__ __launch_bounds__(256)
void prep_kernel(const float* __restrict__ x,  __half* __restrict__ xh,
                 const float* __restrict__ W1, __half* __restrict__ w1t,
                 const float* __restrict__ W2, __half* __restrict__ w2t,
                 float* __restrict__ scores)
{
    __shared__ float t[64][65];
    const int b = blockIdx.x;
    const int tid = threadIdx.x;

    if (b < XB) {
        const int i = (b * 256 + tid) * 4;
        float4 v = *(const float4*)(x + i);
        __half2 a, c;
        a.x = __float2half_rn(v.x);
        a.y = __float2half_rn(v.y);
        c.x = __float2half_rn(v.z);
        c.y = __float2half_rn(v.w);
        *(__half2*)(xh + i)     = a;
        *(__half2*)(xh + i + 2) = c;
    } else if (b < XB + T1B) {
        const int lb = b - XB;
        transpose_tile64(W1, w1t, DIN, HID, lb & 31, lb >> 5, tid, t);
    } else if (b < XB + T1B + T2B) {
        const int lb = b - XB - T1B;
        transpose_tile64(W2, w2t, HID, HID, lb & 31, lb >> 5, tid, t);
    } else {
        const int lb = b - XB - T1B - T2B;
        scores[lb * 1024 + tid * 4 + 0] = 0.0f;
        scores[lb * 1024 + tid * 4 + 1] = 0.0f;
        scores[lb * 1024 + tid * 4 + 2] = 0.0f;
        scores[lb * 1024 + tid * 4 + 3] = 0.0f;
    }
}

// ---------------------------------------------------------------------------
// fp16 single-product GEMM: D = relu(A @ B^T + bias).
// CTA 128x128, 256 threads, warp grid 2x4, warp tile 64x32, KC=64, 2-stage,
// 2 CTAs/SM (occupancy experiment: independent CTAs overlap barrier stalls).
// MODE=1: write single fp16 h1.  MODE=0: fused GEMV into scores.
// ---------------------------------------------------------------------------
#define BM 128
#define BN 128
#define KC 64
#define S_A 0
#define S_B 16384
#define STAGE_BYTES 32768
#define GEMM_SMEM (2 * STAGE_BYTES)   // 65536 per CTA -> 128KB for 2 CTAs/SM

template<int MODE>
__global__ __launch_bounds__(256, 2)
void gemm_mma(const __half* __restrict__ A,
              const __half* __restrict__ B,
              const float* __restrict__ bias,
              int K, int Npitch,
              __half* __restrict__ outH,
              const float* __restrict__ w3,
              float* __restrict__ scores)
{
    extern __shared__ char smem[];
    const uint32_t sb = smem_u32(smem);

    const int tid   = threadIdx.x;
    const int lane  = tid & 31;
    const int w     = tid >> 5;
    const int warpM = w >> 2;          // 0..1 (64 rows)
    const int warpN = w & 3;           // 0..3 (32 cols)
    const int g     = lane >> 2;
    const int tig   = lane & 3;

    const int rowA0 = blockIdx.y * BM;
    const int colB0 = blockIdx.x * BN;
    const int nch   = K / KC;

    float acc[4][4][4];
    #pragma unroll
    for (int mf = 0; mf < 4; mf++)
        #pragma unroll
        for (int nf = 0; nf < 4; nf++)
            #pragma unroll
            for (int e = 0; e < 4; e++)
                acc[mf][nf][e] = 0.0f;

    auto load_chunk = [&](int j, int st) {
        const uint32_t stage = sb + st * STAGE_BYTES;
        const size_t cOff = (size_t)j * KC;
        // A: segs 0..1023, B: segs 1024..2047 (128 rows x 8 segs each)
        #pragma unroll
        for (int u = 0; u < 8; u++) {
            const int seg  = u * 256 + tid;
            const int isB  = seg >> 10;
            const int r    = (seg & 1023) >> 3;
            const int s    = (seg & 7) << 4;
            const uint32_t sw = SW128(r * 128 + s);
            const __half* base = isB ? B : A;
            const int row0 = isB ? colB0 : rowA0;
            const char* gp = (const char*)(base + (size_t)(row0 + r) * K + cOff) + s;
            CPA16(stage + (isB ? S_B : S_A) + sw, gp);
        }
        asm volatile("cp.async.commit_group;");
    };

    const int aRow = warpM * 64 + (lane & 7) + ((lane >> 3) & 1) * 8;
    const int aKb  = ((lane >> 4) & 1) * 16;
    const int bRowBase = warpN * 32 + ((lane >> 4) & 1) * 8 + (lane & 7);
    const int bKb  = ((lane >> 3) & 1) * 16;

    load_chunk(0, 0);

    for (int j = 0; j < nch; j++) {
        __syncthreads();
        if (j + 1 < nch) {
            load_chunk(j + 1, (j + 1) & 1);
            asm volatile("cp.async.wait_group 1;" ::: "memory");
        } else {
            asm volatile("cp.async.wait_group 0;" ::: "memory");
        }
        __syncthreads();

        const uint32_t stage = sb + (j & 1) * STAGE_BYTES;

        #pragma unroll
        for (int ks = 0; ks < 4; ks++) {
            const int kbyte = ks * 32;
            uint32_t a[4][4];
            #pragma unroll
            for (int mf = 0; mf < 4; mf++) {
                const uint32_t off = SW128((aRow + mf * 16) * 128 + kbyte + aKb);
                LDMX4(a[mf][0], a[mf][1], a[mf][2], a[mf][3],
                      stage + S_A + off);
            }
            #pragma unroll
            for (int np = 0; np < 2; np++) {
                const uint32_t off = SW128((bRowBase + np * 16) * 128 + kbyte + bKb);
                uint32_t b0, b1, b2, b3r;
                LDMX4(b0, b1, b2, b3r, stage + S_B + off);
                #pragma unroll
                for (int mf = 0; mf < 4; mf++) {
                    MMAF16(acc[mf][2 * np],     a[mf][0], a[mf][1], a[mf][2], a[mf][3], b0, b1);
                    MMAF16(acc[mf][2 * np + 1], a[mf][0], a[mf][1], a[mf][2], a[mf][3], b2, b3r);
                }
            }
        }
    }

    // ---- epilogue ----
    if constexpr (MODE == 1) {
        #pragma unroll
        for (int mf = 0; mf < 4; mf++) {
            const int r0 = rowA0 + warpM * 64 + mf * 16 + g;
            const int r1 = r0 + 8;
            #pragma unroll
            for (int nf = 0; nf < 4; nf++) {
                const int col = colB0 + warpN * 32 + nf * 8 + tig * 2;
                const float bx = __ldg(bias + col);
                const float by = __ldg(bias + col + 1);
                __half2 h0, h1;
                h0.x = __float2half_rn(fmaxf(acc[mf][nf][0] + bx, 0.0f));
                h0.y = __float2half_rn(fmaxf(acc[mf][nf][1] + by, 0.0f));
                h1.x = __float2half_rn(fmaxf(acc[mf][nf][2] + bx, 0.0f));
                h1.y = __float2half_rn(fmaxf(acc[mf][nf][3] + by, 0.0f));
                *(__half2*)(outH + (size_t)r0 * Npitch + col) = h0;
                *(__half2*)(outH + (size_t)r1 * Npitch + col) = h1;
            }
        }
    } else {
        #pragma unroll
        for (int mf = 0; mf < 4; mf++) {
            const int r0 = rowA0 + warpM * 64 + mf * 16 + g;
            const int r1 = r0 + 8;
            float p0 = 0.0f, p1 = 0.0f;
            #pragma unroll
            for (int nf = 0; nf < 4; nf++) {
                const int col = colB0 + warpN * 32 + nf * 8 + tig * 2;
                const float bx = __ldg(bias + col);
                const float by = __ldg(bias + col + 1);
                const float wx = __ldg(w3 + col);
                const float wy = __ldg(w3 + col + 1);
                p0 += fmaxf(acc[mf][nf][0] + bx, 0.0f) * wx
                    + fmaxf(acc[mf][nf][1] + by, 0.0f) * wy;
                p1 += fmaxf(acc[mf][nf][2] + bx, 0.0f) * wx
                    + fmaxf(acc[mf][nf][3] + by, 0.0f) * wy;
            }
            p0 += __shfl_xor_sync(0xffffffffu, p0, 1);
            p0 += __shfl_xor_sync(0xffffffffu, p0, 2);
            p1 += __shfl_xor_sync(0xffffffffu, p1, 1);
            p1 += __shfl_xor_sync(0xffffffffu, p1, 2);
            if (tig == 0) {
                atomicAdd(scores + r0, p0);
                atomicAdd(scores + r1, p1);
            }
        }
    }
}

// ---------------------------------------------------------------------------
// soft_rank (parallel PAV), b3 folded in (rank shift-invariance)
// ---------------------------------------------------------------------------
__device__ __forceinline__ int pav_merge(int Lbase, int nl, int Rbase, int nr,
                                         int* __restrict__ pst,
                                         int* __restrict__ pcn,
                                         float* __restrict__ psm)
{
    int len = nl;
    for (int t = 0; t < nr; t++) {
        int   cs = pst[Rbase + t];
        int   cc = pcn[Rbase + t];
        float cm = psm[Rbase + t];
        while (len > 0) {
            float ts = psm[Lbase + len - 1];
            int   tc = pcn[Lbase + len - 1];
            if (ts * (float)cc < cm * (float)tc) {
                cm += ts; cc += tc; cs = pst[Lbase + len - 1];
                len--;
            } else break;
        }
        pst[Lbase + len] = cs;
        pcn[Lbase + len] = cc;
        psm[Lbase + len] = cm;
        len++;
    }
    return len;
}

__global__ void softrank_kernel(const float* __restrict__ scores,
                                const float* __restrict__ b3,
                                float* __restrict__ out,
                                int n)
{
    extern __shared__ float smf[];
    float* s   = smf;
    float* psm = s + n;
    int*   idx = (int*)(psm + n);
    int*   pst = idx + n;
    int*   pcn = pst + n;
    int*   cA  = pcn + n;
    int*   cB  = cA + n / 2;

    const int tid = threadIdx.x;
    const int nt  = blockDim.x;
    const float b3v = b3[0];

    for (int i = tid; i < n; i += nt) { s[i] = scores[i] + b3v; idx[i] = i; }
    __syncthreads();

    for (int k = 2; k <= n; k <<= 1) {
        for (int j = k >> 1; j > 0; j >>= 1) {
            for (int i = tid; i < n; i += nt) {
                int ixj = i ^ j;
                if (ixj > i) {
                    bool up = ((i & k) == 0);
                    float a = s[i], b = s[ixj];
                    bool sw = up ? (a < b) : (a > b);
                    if (sw) {
                        s[i] = b; s[ixj] = a;
                        int t = idx[i]; idx[i] = idx[ixj]; idx[ixj] = t;
                    }
                }
            }
            __syncthreads();
        }
    }

    for (int i = tid; i < n; i += nt) {
        pst[i] = i;
        pcn[i] = 1;
        psm[i] = s[i] - (float)(n - i);
    }
    __syncthreads();

    for (int g2 = tid; g2 < n / 2; g2 += nt)
        cA[g2] = pav_merge(2 * g2, 1, 2 * g2 + 1, 1, pst, pcn, psm);
    __syncthreads();

    int* cCur = cA;
    int* cNxt = cB;
    for (int L = 2; (1 << L) <= n; L++) {
        const int half = 1 << (L - 1);
        const int nm = n >> L;
        for (int g2 = tid; g2 < nm; g2 += nt)
            cNxt[g2] = pav_merge((g2 << L), cCur[2 * g2],
                                 (g2 << L) + half, cCur[2 * g2 + 1],
                                 pst, pcn, psm);
        __syncthreads();
        int* t = cCur; cCur = cNxt; cNxt = t;
    }
    const int P = cCur[0];

    for (int i = tid; i < n; i += nt) {
        int lo = 0, hi = P - 1;
        while (lo < hi) {
            int mid = (lo + hi + 1) >> 1;
            if (pst[mid] <= i) lo = mid; else hi = mid - 1;
        }
        float dual = psm[lo] / (float)pcn[lo];
        out[idx[i]] = s[i] - dual;      // rank, original order
        out[n + i]  = scores[i] + b3v;  // scores (with bias)
    }
}

// ---------------------------------------------------------------------------
// Launch
// ---------------------------------------------------------------------------
extern "C" void kernel_launch(void* const* d_in, const int* in_sizes, int n_in,
                              void* d_out, int out_size)
{
    const float* x  = (const float*)d_in[0];
    const float* W1 = (const float*)d_in[1];
    const float* b1 = (const float*)d_in[2];
    const float* W2 = (const float*)d_in[3];
    const float* b2 = (const float*)d_in[4];
    const float* W3 = (const float*)d_in[5];
    const float* b3 = (const float*)d_in[6];
    float* out = (float*)d_out;

    __half *xh, *w1, *w2, *h1;
    float *sc;
    cudaGetSymbolAddress((void**)&xh, g_x);
    cudaGetSymbolAddress((void**)&w1, g_w1);
    cudaGetSymbolAddress((void**)&w2, g_w2);
    cudaGetSymbolAddress((void**)&h1, g_h1);
    cudaGetSymbolAddress((void**)&sc, g_scores);

    // one fused prep launch: convert x, transpose W1/W2, zero scores
    prep_kernel<<<PREP_BLOCKS, 256>>>(x, xh, W1, w1, W2, w2, sc);

    cudaFuncSetAttribute(gemm_mma<1>,
                         cudaFuncAttributeMaxDynamicSharedMemorySize, GEMM_SMEM);
    cudaFuncSetAttribute(gemm_mma<0>,
                         cudaFuncAttributeMaxDynamicSharedMemorySize, GEMM_SMEM);

    // layer 1: relu(x @ W1 + b1) -> h1 (fp16)
    {
        dim3 grid(HID / BN, MB / BM);
        gemm_mma<1><<<grid, 256, GEMM_SMEM>>>(xh, w1, b1, DIN, HID,
                                              h1, nullptr, nullptr);
    }
    // layer 2 + fused GEMV: scores = relu(h1 @ W2 + b2) @ W3
    {
        dim3 grid(HID / BN, MB / BM);
        gemm_mma<0><<<grid, 256, GEMM_SMEM>>>(h1, w2, b2, HID, HID,
                                              nullptr, W3, sc);
    }
    // soft_rank (+ b3)
    {
        size_t smem = (size_t)MB * 6 * sizeof(float);
        cudaFuncSetAttribute(softrank_kernel,
                             cudaFuncAttributeMaxDynamicSharedMemorySize,
                             (int)smem);
        softrank_kernel<<<1, 1024, smem>>>(sc, b3, out, MB);
    }
}

// round 16
// speedup vs baseline: 7.0203x; 1.1307x over previous
#include <cuda_runtime.h>
#include <cuda_fp16.h>
#include <cstdint>

// ---------------------------------------------------------------------------
// Shapes (fixed by the dataset)
// ---------------------------------------------------------------------------
#define MB   4096
#define DIN  512
#define HID  2048

// ---------------------------------------------------------------------------
// Device scratch
// ---------------------------------------------------------------------------
__device__ __half g_x[(size_t)MB * DIN];
__device__ __half g_w1[(size_t)HID * DIN];
__device__ __half g_w2[(size_t)HID * HID];
__device__ __half g_h1[(size_t)MB * HID];
__device__ float g_scores[MB];

// ---------------------------------------------------------------------------
// Helpers
// ---------------------------------------------------------------------------
__device__ __forceinline__ uint32_t smem_u32(const void* p) {
    uint32_t a;
    asm("{ .reg .u64 t; cvta.to.shared.u64 t, %1; cvt.u32.u64 %0, t; }"
        : "=r"(a) : "l"(p));
    return a;
}

#define SW128(o) ((o) ^ (((o) >> 3) & 0x70))

#define CPA16(smem, gptr) \
    asm volatile("cp.async.cg.shared.global [%0], [%1], 16;" \
                 :: "r"(smem), "l"(gptr))

#define LDMX4(r0, r1, r2, r3, addr) \
    asm volatile("ldmatrix.sync.aligned.m8n8.x4.shared.b16 {%0,%1,%2,%3}, [%4];" \
                 : "=r"(r0), "=r"(r1), "=r"(r2), "=r"(r3) : "r"(addr))

#define MMAF16(c, a0, a1, a2, a3, b0, b1) \
    asm volatile("mma.sync.aligned.m16n8k16.row.col.f32.f16.f16.f32 " \
                 "{%0,%1,%2,%3}, {%4,%5,%6,%7}, {%8,%9}, {%0,%1,%2,%3};" \
                 : "+f"((c)[0]), "+f"((c)[1]), "+f"((c)[2]), "+f"((c)[3]) \
                 : "r"(a0), "r"(a1), "r"(a2), "r"(a3), "r"(b0), "r"(b1))

// ---------------------------------------------------------------------------
// Fused prep kernel (unchanged from R15)
// ---------------------------------------------------------------------------
#define XB  2048
#define T1B (HID / 64 * (DIN / 64))
#define T2B (HID / 64 * (HID / 64))
#define PREP_BLOCKS (XB + T1B + T2B + 4)

__device__ __forceinline__ void transpose_tile64(const float* __restrict__ W,
                                                 __half* __restrict__ T,
                                                 int K, int N,
                                                 int bx, int by, int tid,
                                                 float (*t)[65])
{
    const int n0 = bx * 64, k0 = by * 64;
    #pragma unroll
    for (int u = 0; u < 4; u++) {
        const int idx = u * 256 + tid;
        const int r  = idx >> 4;
        const int c4 = idx & 15;
        float4 v = *(const float4*)(W + (size_t)(k0 + r) * N + n0 + c4 * 4);
        t[r][c4 * 4 + 0] = v.x;
        t[r][c4 * 4 + 1] = v.y;
        t[r][c4 * 4 + 2] = v.z;
        t[r][c4 * 4 + 3] = v.w;
    }
    __syncthreads();
    #pragma unroll
    for (int u = 0; u < 8; u++) {
        const int idx = u * 256 + tid;
        const int nr = idx >> 5;
        const int kc = idx & 31;
        __half2 h;
        h.x = __float2half_rn(t[kc * 2][nr]);
        h.y = __float2half_rn(t[kc * 2 + 1][nr]);
        *(__half2*)(T + (size_t)(n0 + nr) * K + k0 + kc * 2) = h;
    }
}

__global__ __launch_bounds__(256)
void prep_kernel(const float* __restrict__ x,  __half* __restrict__ xh,
                 const float* __restrict__ W1, __half* __restrict__ w1t,
                 const float* __restrict__ W2, __half* __restrict__ w2t,
                 float* __restrict__ scores)
{
    __shared__ float t[64][65];
    const int b = blockIdx.x;
    const int tid = threadIdx.x;

    if (b < XB) {
        const int i = (b * 256 + tid) * 4;
        float4 v = *(const float4*)(x + i);
        __half2 a, c;
        a.x = __float2half_rn(v.x);
        a.y = __float2half_rn(v.y);
        c.x = __float2half_rn(v.z);
        c.y = __float2half_rn(v.w);
        *(__half2*)(xh + i)     = a;
        *(__half2*)(xh + i + 2) = c;
    } else if (b < XB + T1B) {
        const int lb = b - XB;
        transpose_tile64(W1, w1t, DIN, HID, lb & 31, lb >> 5, tid, t);
    } else if (b < XB + T1B + T2B) {
        const int lb = b - XB - T1B;
        transpose_tile64(W2, w2t, HID, HID, lb & 31, lb >> 5, tid, t);
    } else {
        const int lb = b - XB - T1B - T2B;
        scores[lb * 1024 + tid * 4 + 0] = 0.0f;
        scores[lb * 1024 + tid * 4 + 1] = 0.0f;
        scores[lb * 1024 + tid * 4 + 2] = 0.0f;
        scores[lb * 1024 + tid * 4 + 3] = 0.0f;
    }
}

// ---------------------------------------------------------------------------
// fp16 single-product GEMM (unchanged from R15): CTA 128x128, 2 CTAs/SM.
// ---------------------------------------------------------------------------
#define BM 128
#define BN 128
#define KC 64
#define S_A 0
#define S_B 16384
#define STAGE_BYTES 32768
#define GEMM_SMEM (2 * STAGE_BYTES)

template<int MODE>
__global__ __launch_bounds__(256, 2)
void gemm_mma(const __half* __restrict__ A,
              const __half* __restrict__ B,
              const float* __restrict__ bias,
              int K, int Npitch,
              __half* __restrict__ outH,
              const float* __restrict__ w3,
              float* __restrict__ scores)
{
    extern __shared__ char smem[];
    const uint32_t sb = smem_u32(smem);

    const int tid   = threadIdx.x;
    const int lane  = tid & 31;
    const int w     = tid >> 5;
    const int warpM = w >> 2;
    const int warpN = w & 3;
    const int g     = lane >> 2;
    const int tig   = lane & 3;

    const int rowA0 = blockIdx.y * BM;
    const int colB0 = blockIdx.x * BN;
    const int nch   = K / KC;

    float acc[4][4][4];
    #pragma unroll
    for (int mf = 0; mf < 4; mf++)
        #pragma unroll
        for (int nf = 0; nf < 4; nf++)
            #pragma unroll
            for (int e = 0; e < 4; e++)
                acc[mf][nf][e] = 0.0f;

    auto load_chunk = [&](int j, int st) {
        const uint32_t stage = sb + st * STAGE_BYTES;
        const size_t cOff = (size_t)j * KC;
        #pragma unroll
        for (int u = 0; u < 8; u++) {
            const int seg  = u * 256 + tid;
            const int isB  = seg >> 10;
            const int r    = (seg & 1023) >> 3;
            const int s    = (seg & 7) << 4;
            const uint32_t sw = SW128(r * 128 + s);
            const __half* base = isB ? B : A;
            const int row0 = isB ? colB0 : rowA0;
            const char* gp = (const char*)(base + (size_t)(row0 + r) * K + cOff) + s;
            CPA16(stage + (isB ? S_B : S_A) + sw, gp);
        }
        asm volatile("cp.async.commit_group;");
    };

    const int aRow = warpM * 64 + (lane & 7) + ((lane >> 3) & 1) * 8;
    const int aKb  = ((lane >> 4) & 1) * 16;
    const int bRowBase = warpN * 32 + ((lane >> 4) & 1) * 8 + (lane & 7);
    const int bKb  = ((lane >> 3) & 1) * 16;

    load_chunk(0, 0);

    for (int j = 0; j < nch; j++) {
        __syncthreads();
        if (j + 1 < nch) {
            load_chunk(j + 1, (j + 1) & 1);
            asm volatile("cp.async.wait_group 1;" ::: "memory");
        } else {
            asm volatile("cp.async.wait_group 0;" ::: "memory");
        }
        __syncthreads();

        const uint32_t stage = sb + (j & 1) * STAGE_BYTES;

        #pragma unroll
        for (int ks = 0; ks < 4; ks++) {
            const int kbyte = ks * 32;
            uint32_t a[4][4];
            #pragma unroll
            for (int mf = 0; mf < 4; mf++) {
                const uint32_t off = SW128((aRow + mf * 16) * 128 + kbyte + aKb);
                LDMX4(a[mf][0], a[mf][1], a[mf][2], a[mf][3],
                      stage + S_A + off);
            }
            #pragma unroll
            for (int np = 0; np < 2; np++) {
                const uint32_t off = SW128((bRowBase + np * 16) * 128 + kbyte + bKb);
                uint32_t b0, b1, b2, b3r;
                LDMX4(b0, b1, b2, b3r, stage + S_B + off);
                #pragma unroll
                for (int mf = 0; mf < 4; mf++) {
                    MMAF16(acc[mf][2 * np],     a[mf][0], a[mf][1], a[mf][2], a[mf][3], b0, b1);
                    MMAF16(acc[mf][2 * np + 1], a[mf][0], a[mf][1], a[mf][2], a[mf][3], b2, b3r);
                }
            }
        }
    }

    if constexpr (MODE == 1) {
        #pragma unroll
        for (int mf = 0; mf < 4; mf++) {
            const int r0 = rowA0 + warpM * 64 + mf * 16 + g;
            const int r1 = r0 + 8;
            #pragma unroll
            for (int nf = 0; nf < 4; nf++) {
                const int col = colB0 + warpN * 32 + nf * 8 + tig * 2;
                const float bx = __ldg(bias + col);
                const float by = __ldg(bias + col + 1);
                __half2 h0, h1;
                h0.x = __float2half_rn(fmaxf(acc[mf][nf][0] + bx, 0.0f));
                h0.y = __float2half_rn(fmaxf(acc[mf][nf][1] + by, 0.0f));
                h1.x = __float2half_rn(fmaxf(acc[mf][nf][2] + bx, 0.0f));
                h1.y = __float2half_rn(fmaxf(acc[mf][nf][3] + by, 0.0f));
                *(__half2*)(outH + (size_t)r0 * Npitch + col) = h0;
                *(__half2*)(outH + (size_t)r1 * Npitch + col) = h1;
            }
        }
    } else {
        #pragma unroll
        for (int mf = 0; mf < 4; mf++) {
            const int r0 = rowA0 + warpM * 64 + mf * 16 + g;
            const int r1 = r0 + 8;
            float p0 = 0.0f, p1 = 0.0f;
            #pragma unroll
            for (int nf = 0; nf < 4; nf++) {
                const int col = colB0 + warpN * 32 + nf * 8 + tig * 2;
                const float bx = __ldg(bias + col);
                const float by = __ldg(bias + col + 1);
                const float wx = __ldg(w3 + col);
                const float wy = __ldg(w3 + col + 1);
                p0 += fmaxf(acc[mf][nf][0] + bx, 0.0f) * wx
                    + fmaxf(acc[mf][nf][1] + by, 0.0f) * wy;
                p1 += fmaxf(acc[mf][nf][2] + bx, 0.0f) * wx
                    + fmaxf(acc[mf][nf][3] + by, 0.0f) * wy;
            }
            p0 += __shfl_xor_sync(0xffffffffu, p0, 1);
            p0 += __shfl_xor_sync(0xffffffffu, p0, 2);
            p1 += __shfl_xor_sync(0xffffffffu, p1, 1);
            p1 += __shfl_xor_sync(0xffffffffu, p1, 2);
            if (tig == 0) {
                atomicAdd(scores + r0, p0);
                atomicAdd(scores + r1, p1);
            }
        }
    }
}

// ---------------------------------------------------------------------------
// soft_rank: hybrid shuffle/shared bitonic sort + parallel PAV.
// Sort phases with j<=16 run in registers via shfl_xor (one barrier per
// batch); phases with j>=32 run in shared over explicit pair indices.
// Swap rule is identical to the plain bitonic (strict compare, descending
// in "up" regions), so the result is bit-identical.
// ---------------------------------------------------------------------------
__device__ __forceinline__ int pav_merge(int Lbase, int nl, int Rbase, int nr,
                                         int* __restrict__ pst,
                                         int* __restrict__ pcn,
                                         float* __restrict__ psm)
{
    int len = nl;
    for (int t = 0; t < nr; t++) {
        int   cs = pst[Rbase + t];
        int   cc = pcn[Rbase + t];
        float cm = psm[Rbase + t];
        while (len > 0) {
            float ts = psm[Lbase + len - 1];
            int   tc = pcn[Lbase + len - 1];
            if (ts * (float)cc < cm * (float)tc) {
                cm += ts; cc += tc; cs = pst[Lbase + len - 1];
                len--;
            } else break;
        }
        pst[Lbase + len] = cs;
        pcn[Lbase + len] = cc;
        psm[Lbase + len] = cm;
        len++;
    }
    return len;
}

__global__ void softrank_kernel(const float* __restrict__ scores,
                                const float* __restrict__ b3,
                                float* __restrict__ out,
                                int n)
{
    extern __shared__ float smf[];
    float* s   = smf;
    float* psm = s + n;
    int*   idx = (int*)(psm + n);
    int*   pst = idx + n;
    int*   pcn = pst + n;
    int*   cA  = pcn + n;
    int*   cB  = cA + n / 2;

    const int tid  = threadIdx.x;
    const int nt   = blockDim.x;
    const int lane = tid & 31;
    const int wid  = tid >> 5;
    const float b3v = b3[0];

    for (int i = tid; i < n; i += nt) { s[i] = scores[i] + b3v; idx[i] = i; }
    __syncthreads();

    const int nseg = n >> 5;              // 32-element segments
    const int segs_per_warp = nseg / (nt >> 5);

    // ---- prologue: rounds k=2..32 entirely in registers ----
    for (int q = 0; q < segs_per_warp; q++) {
        const int i = (wid * segs_per_warp + q) * 32 + lane;
        float v = s[i];
        int   x = idx[i];
        #pragma unroll
        for (int k = 2; k <= 32; k <<= 1) {
            #pragma unroll
            for (int j = k >> 1; j > 0; j >>= 1) {
                float pv = __shfl_xor_sync(0xffffffffu, v, j);
                int   px = __shfl_xor_sync(0xffffffffu, x, j);
                const bool lower = (i & j) == 0;
                const bool up    = (i & k) == 0;
                const float a = lower ? v : pv;
                const float b = lower ? pv : v;
                const bool sw = up ? (a < b) : (a > b);
                if (sw) { v = pv; x = px; }
            }
        }
        s[i] = v; idx[i] = x;
    }
    __syncthreads();

    // ---- rounds k=64..n ----
    for (int k = 64; k <= n; k <<= 1) {
        // shared phases: j = k/2 .. 32 (cross-segment)
        for (int j = k >> 1; j >= 32; j >>= 1) {
            for (int p = tid; p < n / 2; p += nt) {
                const int i   = ((p & ~(j - 1)) << 1) | (p & (j - 1));
                const int ixj = i + j;
                const bool up = (i & k) == 0;
                float a = s[i], b = s[ixj];
                const bool sw = up ? (a < b) : (a > b);
                if (sw) {
                    s[i] = b; s[ixj] = a;
                    int t = idx[i]; idx[i] = idx[ixj]; idx[ixj] = t;
                }
            }
            __syncthreads();
        }
        // register pass: j = 16 .. 1
        for (int q = 0; q < segs_per_warp; q++) {
            const int i = (wid * segs_per_warp + q) * 32 + lane;
            float v = s[i];
            int   x = idx[i];
            const bool up = (i & k) == 0;   // constant across segment (k>=64)
            #pragma unroll
            for (int j = 16; j > 0; j >>= 1) {
                float pv = __shfl_xor_sync(0xffffffffu, v, j);
                int   px = __shfl_xor_sync(0xffffffffu, x, j);
                const bool lower = (i & j) == 0;
                const float a = lower ? v : pv;
                const float b = lower ? pv : v;
                const bool sw = up ? (a < b) : (a > b);
                if (sw) { v = pv; x = px; }
            }
            s[i] = v; idx[i] = x;
        }
        __syncthreads();
    }

    // ---- PAV level-0 pools: y[i] = s[i] - (n - i) ----
    for (int i = tid; i < n; i += nt) {
        pst[i] = i;
        pcn[i] = 1;
        psm[i] = s[i] - (float)(n - i);
    }
    __syncthreads();

    for (int g2 = tid; g2 < n / 2; g2 += nt)
        cA[g2] = pav_merge(2 * g2, 1, 2 * g2 + 1, 1, pst, pcn, psm);
    __syncthreads();

    int* cCur = cA;
    int* cNxt = cB;
    for (int L = 2; (1 << L) <= n; L++) {
        const int half = 1 << (L - 1);
        const int nm = n >> L;
        for (int g2 = tid; g2 < nm; g2 += nt)
            cNxt[g2] = pav_merge((g2 << L), cCur[2 * g2],
                                 (g2 << L) + half, cCur[2 * g2 + 1],
                                 pst, pcn, psm);
        __syncthreads();
        int* t = cCur; cCur = cNxt; cNxt = t;
    }
    const int P = cCur[0];

    for (int i = tid; i < n; i += nt) {
        int lo = 0, hi = P - 1;
        while (lo < hi) {
            int mid = (lo + hi + 1) >> 1;
            if (pst[mid] <= i) lo = mid; else hi = mid - 1;
        }
        float dual = psm[lo] / (float)pcn[lo];
        out[idx[i]] = s[i] - dual;      // rank, original order
        out[n + i]  = scores[i] + b3v;  // scores (with bias)
    }
}

// ---------------------------------------------------------------------------
// Launch
// ---------------------------------------------------------------------------
extern "C" void kernel_launch(void* const* d_in, const int* in_sizes, int n_in,
                              void* d_out, int out_size)
{
    const float* x  = (const float*)d_in[0];
    const float* W1 = (const float*)d_in[1];
    const float* b1 = (const float*)d_in[2];
    const float* W2 = (const float*)d_in[3];
    const float* b2 = (const float*)d_in[4];
    const float* W3 = (const float*)d_in[5];
    const float* b3 = (const float*)d_in[6];
    float* out = (float*)d_out;

    __half *xh, *w1, *w2, *h1;
    float *sc;
    cudaGetSymbolAddress((void**)&xh, g_x);
    cudaGetSymbolAddress((void**)&w1, g_w1);
    cudaGetSymbolAddress((void**)&w2, g_w2);
    cudaGetSymbolAddress((void**)&h1, g_h1);
    cudaGetSymbolAddress((void**)&sc, g_scores);

    // one fused prep launch: convert x, transpose W1/W2, zero scores
    prep_kernel<<<PREP_BLOCKS, 256>>>(x, xh, W1, w1, W2, w2, sc);

    cudaFuncSetAttribute(gemm_mma<1>,
                         cudaFuncAttributeMaxDynamicSharedMemorySize, GEMM_SMEM);
    cudaFuncSetAttribute(gemm_mma<0>,
                         cudaFuncAttributeMaxDynamicSharedMemorySize, GEMM_SMEM);

    // layer 1: relu(x @ W1 + b1) -> h1 (fp16)
    {
        dim3 grid(HID / BN, MB / BM);
        gemm_mma<1><<<grid, 256, GEMM_SMEM>>>(xh, w1, b1, DIN, HID,
                                              h1, nullptr, nullptr);
    }
    // layer 2 + fused GEMV: scores = relu(h1 @ W2 + b2) @ W3
    {
        dim3 grid(HID / BN, MB / BM);
        gemm_mma<0><<<grid, 256, GEMM_SMEM>>>(h1, w2, b2, HID, HID,
                                              nullptr, W3, sc);
    }
    // soft_rank (+ b3)
    {
        size_t smem = (size_t)MB * 6 * sizeof(float);
        cudaFuncSetAttribute(softrank_kernel,
                             cudaFuncAttributeMaxDynamicSharedMemorySize,
                             (int)smem);
        softrank_kernel<<<1, 1024, smem>>>(sc, b3, out, MB);
    }
}